// round 5
// baseline (speedup 1.0000x reference)
#include <cuda_runtime.h>
#include <math.h>
#include <stdint.h>

// ---------------- problem constants ----------------
#define T_LEN 16384
#define HH    200
#define NP    3200      // POOL*H
#define PO    16

// ---------------- device scratch (static; no allocations allowed) ----------------
__device__ float g_G[2u * T_LEN * NP];        // [hd][t][n'], n' = j*16+p  (419 MB)
__device__ float g_m1[2u * T_LEN * HH];       // [hd][t][j]
__device__ float g_w2a[2 * NP * 400];         // reordered fc2w[:, :400]
__device__ float g_w2b[2 * NP * 200];         // reordered fc2w[:, 400:600]
__device__ float g_b2 [2 * NP];
__device__ float g_w3 [2 * NP * 200];         // reordered fc3w
__device__ float g_b3 [2 * NP];

struct DecState {
    float h[HH];
    float c[HH];
    float r[2][HH];
    float v[2][NP];
    unsigned long long amax[2];
    int start, end, done;
};
__device__ DecState g_st;

// ---------------- init ----------------
__global__ void k_init() {
    int tid = threadIdx.x;
    for (int j = tid; j < HH; j += blockDim.x) { g_st.h[j] = 0.f; g_st.c[j] = 0.f; }
    if (tid == 0) { g_st.start = 0; g_st.end = 0; g_st.done = 0; }
}

// ---------------- weight reorder: n' = j*16 + p  <- original row p*200+j ----------
__global__ void k_prep(const float* __restrict__ s2w, const float* __restrict__ s2b,
                       const float* __restrict__ s3w, const float* __restrict__ s3b,
                       const float* __restrict__ e2w, const float* __restrict__ e2b,
                       const float* __restrict__ e3w, const float* __restrict__ e3b) {
    int row = blockIdx.x;                 // 0..6399
    int hd  = row / NP;
    int np  = row - hd * NP;
    int j = np >> 4, p = np & 15;
    int src = p * HH + j;
    const float* w2 = hd ? e2w : s2w;
    const float* b2 = hd ? e2b : s2b;
    const float* w3 = hd ? e3w : s3w;
    const float* b3 = hd ? e3b : s3b;
    const float* w2row = w2 + (size_t)src * 600;
    const float* w3row = w3 + (size_t)src * 200;
    float* dA = g_w2a + (size_t)row * 400;
    float* dB = g_w2b + (size_t)row * 200;
    float* dW = g_w3  + (size_t)row * 200;
    for (int k = threadIdx.x; k < 400; k += blockDim.x) dA[k] = w2row[k];
    for (int k = threadIdx.x; k < 200; k += blockDim.x) {
        dB[k] = w2row[400 + k];
        dW[k] = w3row[k];
    }
    if (threadIdx.x == 0) { g_b2[row] = b2[src]; g_b3[row] = b3[src]; }
}

// ---------------- G = U @ w2a^T  (NT SGEMM, 128x128x16 tiles, 8x8/thread) -------
__global__ void __launch_bounds__(256) k_gemm_G(const float* __restrict__ U) {
    __shared__ float AsT[16][132];
    __shared__ float BsT[16][132];
    int hd = blockIdx.z;
    int n0 = blockIdx.x * 128;
    int t0 = blockIdx.y * 128;
    int tid = threadIdx.x;
    int ty = tid >> 4, tx = tid & 15;
    int lr = tid >> 2;        // 0..63
    int lq = tid & 3;         // 0..3

    const float* A = U + (size_t)t0 * 400;
    const float* B = g_w2a + ((size_t)hd * NP + n0) * 400;

    float acc[8][8];
#pragma unroll
    for (int i = 0; i < 8; i++)
#pragma unroll
        for (int j = 0; j < 8; j++) acc[i][j] = 0.f;

    for (int kt = 0; kt < 400; kt += 16) {
#pragma unroll
        for (int h = 0; h < 2; h++) {
            int r = lr + h * 64;
            float4 a4 = *(const float4*)(A + (size_t)r * 400 + kt + lq * 4);
            float4 b4 = *(const float4*)(B + (size_t)r * 400 + kt + lq * 4);
            AsT[lq * 4 + 0][r] = a4.x; AsT[lq * 4 + 1][r] = a4.y;
            AsT[lq * 4 + 2][r] = a4.z; AsT[lq * 4 + 3][r] = a4.w;
            BsT[lq * 4 + 0][r] = b4.x; BsT[lq * 4 + 1][r] = b4.y;
            BsT[lq * 4 + 2][r] = b4.z; BsT[lq * 4 + 3][r] = b4.w;
        }
        __syncthreads();
#pragma unroll
        for (int kk = 0; kk < 16; kk++) {
            float4 a0 = *(const float4*)&AsT[kk][ty * 8];
            float4 a1 = *(const float4*)&AsT[kk][ty * 8 + 4];
            float4 b0 = *(const float4*)&BsT[kk][tx * 8];
            float4 b1 = *(const float4*)&BsT[kk][tx * 8 + 4];
            float av[8] = {a0.x, a0.y, a0.z, a0.w, a1.x, a1.y, a1.z, a1.w};
            float bv[8] = {b0.x, b0.y, b0.z, b0.w, b1.x, b1.y, b1.z, b1.w};
#pragma unroll
            for (int i = 0; i < 8; i++)
#pragma unroll
                for (int j = 0; j < 8; j++) acc[i][j] += av[i] * bv[j];
        }
        __syncthreads();
    }
#pragma unroll
    for (int i = 0; i < 8; i++) {
        float* dst = g_G + ((size_t)hd * T_LEN + t0 + ty * 8 + i) * NP + n0 + tx * 8;
        *(float4*)(dst)     = make_float4(acc[i][0], acc[i][1], acc[i][2], acc[i][3]);
        *(float4*)(dst + 4) = make_float4(acc[i][4], acc[i][5], acc[i][6], acc[i][7]);
    }
}

// ---------------- LSTM step + r vectors (single block) ----------------
__global__ void __launch_bounds__(256) k_lstm(const float* __restrict__ U,
        const float* __restrict__ Wih, const float* __restrict__ Whh,
        const float* __restrict__ bih, const float* __restrict__ bhh,
        const float* __restrict__ s1w, const float* __restrict__ e1w) {
    if (g_st.done) return;
    __shared__ float xs[800];
    __shared__ float gs[800];
    __shared__ float hs[HH];
    __shared__ float hn_s[HH];
    int tid = threadIdx.x;
    int st = g_st.start, en = g_st.end;
    for (int k = tid; k < 400; k += 256) {
        xs[k]       = U[(size_t)st * 400 + k];
        xs[400 + k] = U[(size_t)en * 400 + k];
    }
    for (int k = tid; k < HH; k += 256) hs[k] = g_st.h[k];
    if (tid == 0) { g_st.amax[0] = 0ull; g_st.amax[1] = 0ull; }
    __syncthreads();
    for (int g = tid; g < 800; g += 256) {
        float acc = bih[g] + bhh[g];
        const float* wr = Wih + (size_t)g * 800;
        for (int k = 0; k < 800; k++) acc += wr[k] * xs[k];
        const float* wh = Whh + (size_t)g * HH;
        for (int k = 0; k < HH; k++) acc += wh[k] * hs[k];
        gs[g] = acc;
    }
    __syncthreads();
    for (int j = tid; j < HH; j += 256) {
        float ig = 1.f / (1.f + expf(-gs[j]));
        float fg = 1.f / (1.f + expf(-gs[200 + j]));
        float gg = tanhf(gs[400 + j]);
        float og = 1.f / (1.f + expf(-gs[600 + j]));
        float cn = fg * g_st.c[j] + ig * gg;
        float hn = og * tanhf(cn);
        g_st.c[j] = cn; g_st.h[j] = hn; hn_s[j] = hn;
    }
    __syncthreads();
    // r_hd = tanh(fc1w @ [h_new, U[start], U[end]])
    for (int idx = tid; idx < 2 * HH; idx += 256) {
        int hd = idx / HH, j = idx % HH;
        const float* w = (hd ? e1w : s1w) + (size_t)j * 1000;
        float acc = 0.f;
        for (int k = 0; k < HH; k++)  acc += w[k] * hn_s[k];
        for (int k = 0; k < 800; k++) acc += w[200 + k] * xs[k];
        g_st.r[hd][j] = tanhf(acc);
    }
}

// ---------------- v = w2b_r @ r + b2  (one warp per output) ----------------
__global__ void k_v() {
    if (g_st.done) return;
    int gw = (blockIdx.x * blockDim.x + threadIdx.x) >> 5;
    int lane = threadIdx.x & 31;
    if (gw >= 2 * NP) return;
    int hd = gw / NP, n = gw - hd * NP;
    const float* w = g_w2b + ((size_t)hd * NP + n) * 200;
    const float* r = g_st.r[hd];
    float acc = 0.f;
    for (int k = lane; k < 200; k += 32) acc += w[k] * r[k];
    for (int o = 16; o; o >>= 1) acc += __shfl_xor_sync(0xffffffffu, acc, o);
    if (lane == 0) g_st.v[hd][n] = acc + g_b2[hd * NP + n];
}

// ---------------- m1 = maxout_pool(G + v) ----------------
__global__ void k_m1() {
    if (g_st.done) return;
    int idx = blockIdx.x * blockDim.x + threadIdx.x;    // 0 .. 2*16384*200-1
    const int per = T_LEN * HH;
    if (idx >= 2 * per) return;
    int hd = idx / per;
    int rem = idx - hd * per;
    int t = rem / HH, j = rem - t * HH;
    const float* gp = g_G + ((size_t)hd * T_LEN + t) * NP + j * 16;
    const float* vp = g_st.v[hd] + j * 16;
    float m = -3.4e38f;
#pragma unroll
    for (int p = 0; p < 16; p++) m = fmaxf(m, gp[p] + vp[p]);
    g_m1[((size_t)hd * T_LEN + t) * HH + j] = m;
}

// ---------------- fused: fc3 GEMM + maxout -> m2 (chunked); fc4 -> alpha; argmax
// smem (floats): m1sT[200][128]=25600 | BsT[200][64]=12800 | w4T[400][16]=6400
//                m2c[128][4]=512 | b4s[16]
#define SC_M1   0
#define SC_B    25600
#define SC_W4   38400
#define SC_M2   44800
#define SC_B4   45312
#define SCORE_SMEM_FLOATS 45328
#define SCORE_SMEM_BYTES  (SCORE_SMEM_FLOATS * 4)

__global__ void __launch_bounds__(256, 1) k_score(
        const float* __restrict__ s4w, const float* __restrict__ s4b,
        const float* __restrict__ e4w, const float* __restrict__ e4b,
        float* __restrict__ out, int iter) {
    extern __shared__ float sm[];
    int hd = blockIdx.y;
    int t0 = blockIdx.x * 128;
    float* outh = out + (size_t)hd * 4 * T_LEN + (size_t)iter * T_LEN;

    if (g_st.done) {       // frozen: alpha[iter] = alpha[iter-1]  (iter >= 2 here)
        for (int t = threadIdx.x; t < 128; t += 256)
            outh[t0 + t] = outh[t0 + t - T_LEN];
        return;
    }

    float* m1sT = sm + SC_M1;   // [200][128]
    float* BsT  = sm + SC_B;    // [200][64]
    float* w4T  = sm + SC_W4;   // [400][16]  w4T[k][p] = w4[p][k]
    float* m2c  = sm + SC_M2;   // [128][4]
    float* b4s  = sm + SC_B4;   // [16]

    int tid = threadIdx.x;
    const float* w4  = hd ? e4w : s4w;
    const float* b4g = hd ? e4b : s4b;
    for (int i = tid; i < 6400; i += 256) {
        int k = i >> 4, p = i & 15;
        w4T[i] = w4[(size_t)p * 400 + k];
    }
    if (tid < 16) b4s[tid] = b4g[tid];

    {   // load m1 block transposed: m1sT[k][m]
        int m = tid & 127, g0 = tid >> 7;
        const float* src = g_m1 + ((size_t)hd * T_LEN + t0 + m) * HH;
        for (int q = g0; q < 50; q += 2) {
            float4 v4 = *(const float4*)(src + q * 4);
            m1sT[(q * 4 + 0) * 128 + m] = v4.x;
            m1sT[(q * 4 + 1) * 128 + m] = v4.y;
            m1sT[(q * 4 + 2) * 128 + m] = v4.z;
            m1sT[(q * 4 + 3) * 128 + m] = v4.w;
        }
    }

    int ty = tid >> 4, tx = tid & 15;   // rows ty*8..+7, cols tx*4..+3
    int row2 = tid >> 1, half = tid & 1;  // fc4 mapping
    float p4[8];                          // fc4 accumulators (8 p's)
#pragma unroll
    for (int i = 0; i < 8; i++) p4[i] = 0.f;

    for (int nc = 0; nc < 50; nc++) {
        int n0 = nc * 64;
        {   // stage w3 chunk transposed: BsT[k][n]
            int n = tid & 63, q0 = tid >> 6;
            const float* src = g_w3 + ((size_t)hd * NP + n0 + n) * 200;
            for (int q = q0; q < 50; q += 4) {
                float4 v4 = *(const float4*)(src + q * 4);
                BsT[(q * 4 + 0) * 64 + n] = v4.x;
                BsT[(q * 4 + 1) * 64 + n] = v4.y;
                BsT[(q * 4 + 2) * 64 + n] = v4.z;
                BsT[(q * 4 + 3) * 64 + n] = v4.w;
            }
        }
        __syncthreads();

        float acc[8][4];
#pragma unroll
        for (int i = 0; i < 8; i++)
#pragma unroll
            for (int j = 0; j < 4; j++) acc[i][j] = 0.f;

#pragma unroll 2
        for (int k = 0; k < 200; k++) {
            float4 a0 = *(const float4*)(m1sT + k * 128 + ty * 8);
            float4 a1 = *(const float4*)(m1sT + k * 128 + ty * 8 + 4);
            float4 bv = *(const float4*)(BsT + k * 64 + tx * 4);
            float av[8] = {a0.x, a0.y, a0.z, a0.w, a1.x, a1.y, a1.z, a1.w};
#pragma unroll
            for (int i = 0; i < 8; i++) {
                acc[i][0] += av[i] * bv.x; acc[i][1] += av[i] * bv.y;
                acc[i][2] += av[i] * bv.z; acc[i][3] += av[i] * bv.w;
            }
        }

        // maxout over 16 cols (4 cols/thread, then shfl over tx-groups of 4)
        float b3v0 = g_b3[hd * NP + n0 + tx * 4 + 0];
        float b3v1 = g_b3[hd * NP + n0 + tx * 4 + 1];
        float b3v2 = g_b3[hd * NP + n0 + tx * 4 + 2];
        float b3v3 = g_b3[hd * NP + n0 + tx * 4 + 3];
#pragma unroll
        for (int i = 0; i < 8; i++) {
            float m = fmaxf(fmaxf(acc[i][0] + b3v0, acc[i][1] + b3v1),
                            fmaxf(acc[i][2] + b3v2, acc[i][3] + b3v3));
            m = fmaxf(m, __shfl_xor_sync(0xffffffffu, m, 1));
            m = fmaxf(m, __shfl_xor_sync(0xffffffffu, m, 2));
            if ((tx & 3) == 0) m2c[(ty * 8 + i) * 4 + (tx >> 2)] = m;
        }
        __syncthreads();

        // fc4 partial: p4[pp] += m2c[row][jl] * w4[p][200 + nc*4 + jl]
        {
            float mv0 = m2c[row2 * 4 + 0], mv1 = m2c[row2 * 4 + 1];
            float mv2 = m2c[row2 * 4 + 2], mv3 = m2c[row2 * 4 + 3];
            const float* w0 = w4T + (200 + nc * 4) * 16 + half * 8;
#pragma unroll
            for (int pp = 0; pp < 8; pp++)
                p4[pp] += mv0 * w0[pp] + mv1 * w0[16 + pp] +
                          mv2 * w0[32 + pp] + mv3 * w0[48 + pp];
        }
        __syncthreads();   // m2c consumed; BsT free for next chunk
    }

    // fc4 m1-part + pool max + output + packed argmax
    {
        for (int k = 0; k < 200; k++) {
            float mval = m1sT[k * 128 + row2];
            const float* wp = w4T + k * 16 + half * 8;
#pragma unroll
            for (int pp = 0; pp < 8; pp++) p4[pp] += mval * wp[pp];
        }
        float v = -3.4e38f;
#pragma unroll
        for (int pp = 0; pp < 8; pp++) v = fmaxf(v, p4[pp] + b4s[half * 8 + pp]);
        v = fmaxf(v, __shfl_xor_sync(0xffffffffu, v, 1));
        if (half == 0) {
            int t = t0 + row2;
            outh[t] = v;
            unsigned key = __float_as_uint(v);
            key = (key & 0x80000000u) ? ~key : (key | 0x80000000u);
            unsigned long long pk =
                ((unsigned long long)key << 32) | (unsigned long long)(0xFFFFFFFFu - (unsigned)t);
            atomicMax(&g_st.amax[hd], pk);
        }
    }
}

// ---------------- argmax decode + done/start/end update ----------------
__global__ void k_update(int iter) {
    if (g_st.done) return;
    unsigned long long a0 = g_st.amax[0], a1 = g_st.amax[1];
    int ns = (int)(0xFFFFFFFFu - (unsigned)(a0 & 0xFFFFFFFFull));
    int ne = (int)(0xFFFFFFFFu - (unsigned)(a1 & 0xFFFFFFFFull));
    if (iter > 0 && ns == g_st.start && ne == g_st.end) g_st.done = 1;
    g_st.start = ns;
    g_st.end = ne;
}

// ---------------- launch ----------------
extern "C" void kernel_launch(void* const* d_in, const int* in_sizes, int n_in,
                              void* d_out, int out_size) {
    const float* U    = (const float*)d_in[0];
    const float* Wih  = (const float*)d_in[1];
    const float* Whh  = (const float*)d_in[2];
    const float* bih  = (const float*)d_in[3];
    const float* bhh  = (const float*)d_in[4];
    const float* s1w  = (const float*)d_in[5];
    const float* s2w  = (const float*)d_in[6];
    const float* s2b  = (const float*)d_in[7];
    const float* s3w  = (const float*)d_in[8];
    const float* s3b  = (const float*)d_in[9];
    const float* s4w  = (const float*)d_in[10];
    const float* s4b  = (const float*)d_in[11];
    const float* e1w  = (const float*)d_in[12];
    const float* e2w  = (const float*)d_in[13];
    const float* e2b  = (const float*)d_in[14];
    const float* e3w  = (const float*)d_in[15];
    const float* e3b  = (const float*)d_in[16];
    const float* e4w  = (const float*)d_in[17];
    const float* e4b  = (const float*)d_in[18];
    float* out = (float*)d_out;

    static int attr_done = 0;
    if (!attr_done) {
        cudaFuncSetAttribute(k_score, cudaFuncAttributeMaxDynamicSharedMemorySize, SCORE_SMEM_BYTES);
        attr_done = 1;
    }

    k_init<<<1, 256>>>();
    k_prep<<<6400, 128>>>(s2w, s2b, s3w, s3b, e2w, e2b, e3w, e3b);

    dim3 gG(NP / 128, T_LEN / 128, 2);
    k_gemm_G<<<gG, 256>>>(U);

    for (int it = 0; it < 4; ++it) {
        k_lstm<<<1, 256>>>(U, Wih, Whh, bih, bhh, s1w, e1w);
        k_v<<<800, 256>>>();
        k_m1<<<(2 * T_LEN * HH + 255) / 256, 256>>>();
        dim3 gs(T_LEN / 128, 2);
        k_score<<<gs, 256, SCORE_SMEM_BYTES>>>(s4w, s4b, e4w, e4b, out, it);
        if (it < 3) k_update<<<1, 1>>>(it);
    }
}

// round 6
// speedup vs baseline: 1.2354x; 1.2354x over previous
#include <cuda_runtime.h>
#include <math.h>
#include <stdint.h>

// ---------------- problem constants ----------------
#define T_LEN 16384
#define HH    200
#define NP    3200      // POOL*H
#define PO    16

// ---------------- device scratch (static; no allocations allowed) ----------------
__device__ float g_G[2u * T_LEN * NP];        // [hd][t][n'], n' = j*16+p  (419 MB)
__device__ float g_m1[2u * T_LEN * HH];       // [hd][t][j]
__device__ float g_w2a[2 * NP * 400];         // reordered fc2w[:, :400]
__device__ float g_w2b[2 * NP * 200];         // reordered fc2w[:, 400:600]
__device__ float g_b2 [2 * NP];
__device__ float g_w3 [2 * NP * 200];         // reordered fc3w
__device__ float g_b3 [2 * NP];
__device__ float g_gates[800];

struct DecState {
    float h[HH];
    float c[HH];
    float r[2][HH];
    float v[2][NP];
    unsigned long long amax[2];
    int start, end, done;
};
__device__ DecState g_st;

// ---------------- init ----------------
__global__ void k_init() {
    int tid = threadIdx.x;
    for (int j = tid; j < HH; j += blockDim.x) { g_st.h[j] = 0.f; g_st.c[j] = 0.f; }
    if (tid == 0) { g_st.start = 0; g_st.end = 0; g_st.done = 0; }
}

// ---------------- weight reorder: n' = j*16 + p  <- original row p*200+j ----------
__global__ void k_prep(const float* __restrict__ s2w, const float* __restrict__ s2b,
                       const float* __restrict__ s3w, const float* __restrict__ s3b,
                       const float* __restrict__ e2w, const float* __restrict__ e2b,
                       const float* __restrict__ e3w, const float* __restrict__ e3b) {
    int row = blockIdx.x;                 // 0..6399
    int hd  = row / NP;
    int np  = row - hd * NP;
    int j = np >> 4, p = np & 15;
    int src = p * HH + j;
    const float* w2 = hd ? e2w : s2w;
    const float* b2 = hd ? e2b : s2b;
    const float* w3 = hd ? e3w : s3w;
    const float* b3 = hd ? e3b : s3b;
    const float* w2row = w2 + (size_t)src * 600;
    const float* w3row = w3 + (size_t)src * 200;
    float* dA = g_w2a + (size_t)row * 400;
    float* dB = g_w2b + (size_t)row * 200;
    float* dW = g_w3  + (size_t)row * 200;
    for (int k = threadIdx.x; k < 400; k += blockDim.x) dA[k] = w2row[k];
    for (int k = threadIdx.x; k < 200; k += blockDim.x) {
        dB[k] = w2row[400 + k];
        dW[k] = w3row[k];
    }
    if (threadIdx.x == 0) { g_b2[row] = b2[src]; g_b3[row] = b3[src]; }
}

// ---------------- G = U @ w2a^T  (NT SGEMM, 128x128x16 tiles, 8x8/thread) -------
__global__ void __launch_bounds__(256) k_gemm_G(const float* __restrict__ U) {
    __shared__ float AsT[16][132];
    __shared__ float BsT[16][132];
    int hd = blockIdx.z;
    int n0 = blockIdx.x * 128;
    int t0 = blockIdx.y * 128;
    int tid = threadIdx.x;
    int ty = tid >> 4, tx = tid & 15;
    int lr = tid >> 2;        // 0..63
    int lq = tid & 3;         // 0..3

    const float* A = U + (size_t)t0 * 400;
    const float* B = g_w2a + ((size_t)hd * NP + n0) * 400;

    float acc[8][8];
#pragma unroll
    for (int i = 0; i < 8; i++)
#pragma unroll
        for (int j = 0; j < 8; j++) acc[i][j] = 0.f;

    for (int kt = 0; kt < 400; kt += 16) {
#pragma unroll
        for (int h = 0; h < 2; h++) {
            int r = lr + h * 64;
            float4 a4 = *(const float4*)(A + (size_t)r * 400 + kt + lq * 4);
            float4 b4 = *(const float4*)(B + (size_t)r * 400 + kt + lq * 4);
            AsT[lq * 4 + 0][r] = a4.x; AsT[lq * 4 + 1][r] = a4.y;
            AsT[lq * 4 + 2][r] = a4.z; AsT[lq * 4 + 3][r] = a4.w;
            BsT[lq * 4 + 0][r] = b4.x; BsT[lq * 4 + 1][r] = b4.y;
            BsT[lq * 4 + 2][r] = b4.z; BsT[lq * 4 + 3][r] = b4.w;
        }
        __syncthreads();
#pragma unroll
        for (int kk = 0; kk < 16; kk++) {
            float4 a0 = *(const float4*)&AsT[kk][ty * 8];
            float4 a1 = *(const float4*)&AsT[kk][ty * 8 + 4];
            float4 b0 = *(const float4*)&BsT[kk][tx * 8];
            float4 b1 = *(const float4*)&BsT[kk][tx * 8 + 4];
            float av[8] = {a0.x, a0.y, a0.z, a0.w, a1.x, a1.y, a1.z, a1.w};
            float bv[8] = {b0.x, b0.y, b0.z, b0.w, b1.x, b1.y, b1.z, b1.w};
#pragma unroll
            for (int i = 0; i < 8; i++)
#pragma unroll
                for (int j = 0; j < 8; j++) acc[i][j] += av[i] * bv[j];
        }
        __syncthreads();
    }
#pragma unroll
    for (int i = 0; i < 8; i++) {
        float* dst = g_G + ((size_t)hd * T_LEN + t0 + ty * 8 + i) * NP + n0 + tx * 8;
        *(float4*)(dst)     = make_float4(acc[i][0], acc[i][1], acc[i][2], acc[i][3]);
        *(float4*)(dst + 4) = make_float4(acc[i][4], acc[i][5], acc[i][6], acc[i][7]);
    }
}

// ---------------- LSTM gates: one warp per gate (800 warps) ----------------
__global__ void __launch_bounds__(256) k_gates(const float* __restrict__ U,
        const float* __restrict__ Wih, const float* __restrict__ Whh,
        const float* __restrict__ bih, const float* __restrict__ bhh) {
    if (g_st.done) return;
    int g = blockIdx.x * 8 + (threadIdx.x >> 5);
    int lane = threadIdx.x & 31;
    const float* Us = U + (size_t)g_st.start * 400;
    const float* Ue = U + (size_t)g_st.end * 400;
    const float* wr = Wih + (size_t)g * 800;
    const float* wh = Whh + (size_t)g * HH;
    float acc = 0.f;
#pragma unroll
    for (int q = 0; q < 3; q++) {            // k = lane*4 + q*128, covers 0..383
        int k = lane * 4 + q * 128;
        float4 w0 = *(const float4*)(wr + k);
        float4 w1 = *(const float4*)(wr + 400 + k);
        float4 x0 = *(const float4*)(Us + k);
        float4 x1 = *(const float4*)(Ue + k);
        acc += w0.x * x0.x + w0.y * x0.y + w0.z * x0.z + w0.w * x0.w;
        acc += w1.x * x1.x + w1.y * x1.y + w1.z * x1.z + w1.w * x1.w;
    }
    {   // tail k = 384..399 (4 lanes)
        int k = 384 + lane * 4;
        if (k < 400) {
            float4 w0 = *(const float4*)(wr + k);
            float4 w1 = *(const float4*)(wr + 400 + k);
            float4 x0 = *(const float4*)(Us + k);
            float4 x1 = *(const float4*)(Ue + k);
            acc += w0.x * x0.x + w0.y * x0.y + w0.z * x0.z + w0.w * x0.w;
            acc += w1.x * x1.x + w1.y * x1.y + w1.z * x1.z + w1.w * x1.w;
        }
    }
    for (int k = lane; k < HH; k += 32) acc += wh[k] * g_st.h[k];
    for (int o = 16; o; o >>= 1) acc += __shfl_xor_sync(0xffffffffu, acc, o);
    if (lane == 0) g_gates[g] = acc + bih[g] + bhh[g];
}

// ---------------- activation + state update (1 small block) ----------------
__global__ void k_act() {
    if (threadIdx.x == 0) { g_st.amax[0] = 0ull; g_st.amax[1] = 0ull; }
    if (g_st.done) return;
    int j = threadIdx.x;
    if (j < HH) {
        float ig = 1.f / (1.f + expf(-g_gates[j]));
        float fg = 1.f / (1.f + expf(-g_gates[200 + j]));
        float gg = tanhf(g_gates[400 + j]);
        float og = 1.f / (1.f + expf(-g_gates[600 + j]));
        float cn = fg * g_st.c[j] + ig * gg;
        g_st.c[j] = cn;
        g_st.h[j] = og * tanhf(cn);
    }
}

// ---------------- r = tanh(fc1w @ [h, U[start], U[end]]) : warp per output ------
__global__ void __launch_bounds__(256) k_r(const float* __restrict__ U,
        const float* __restrict__ s1w, const float* __restrict__ e1w) {
    if (g_st.done) return;
    int idx = blockIdx.x * 8 + (threadIdx.x >> 5);   // 0..399
    int lane = threadIdx.x & 31;
    int hd = idx / HH, j = idx - hd * HH;
    const float* w = (hd ? e1w : s1w) + (size_t)j * 1000;
    const float* Us = U + (size_t)g_st.start * 400;
    const float* Ue = U + (size_t)g_st.end * 400;
    float acc = 0.f;
    for (int k = lane; k < HH; k += 32) acc += w[k] * g_st.h[k];
#pragma unroll
    for (int q = 0; q < 3; q++) {
        int k = lane * 4 + q * 128;
        float4 w0 = *(const float4*)(w + 200 + k);
        float4 w1 = *(const float4*)(w + 600 + k);
        float4 x0 = *(const float4*)(Us + k);
        float4 x1 = *(const float4*)(Ue + k);
        acc += w0.x * x0.x + w0.y * x0.y + w0.z * x0.z + w0.w * x0.w;
        acc += w1.x * x1.x + w1.y * x1.y + w1.z * x1.z + w1.w * x1.w;
    }
    {
        int k = 384 + lane * 4;
        if (k < 400) {
            float4 w0 = *(const float4*)(w + 200 + k);
            float4 w1 = *(const float4*)(w + 600 + k);
            float4 x0 = *(const float4*)(Us + k);
            float4 x1 = *(const float4*)(Ue + k);
            acc += w0.x * x0.x + w0.y * x0.y + w0.z * x0.z + w0.w * x0.w;
            acc += w1.x * x1.x + w1.y * x1.y + w1.z * x1.z + w1.w * x1.w;
        }
    }
    for (int o = 16; o; o >>= 1) acc += __shfl_xor_sync(0xffffffffu, acc, o);
    if (lane == 0) g_st.r[hd][j] = tanhf(acc);
}

// ---------------- v = w2b_r @ r + b2  (one warp per output) ----------------
__global__ void k_v() {
    if (g_st.done) return;
    int gw = (blockIdx.x * blockDim.x + threadIdx.x) >> 5;
    int lane = threadIdx.x & 31;
    if (gw >= 2 * NP) return;
    int hd = gw / NP, n = gw - hd * NP;
    const float* w = g_w2b + ((size_t)hd * NP + n) * 200;
    const float* r = g_st.r[hd];
    float acc = 0.f;
    for (int k = lane; k < 200; k += 32) acc += w[k] * r[k];
    for (int o = 16; o; o >>= 1) acc += __shfl_xor_sync(0xffffffffu, acc, o);
    if (lane == 0) g_st.v[hd][n] = acc + g_b2[hd * NP + n];
}

// ---------------- m1 = maxout_pool(G + v) ----------------
__global__ void k_m1() {
    if (g_st.done) return;
    int idx = blockIdx.x * blockDim.x + threadIdx.x;    // 0 .. 2*16384*200-1
    const int per = T_LEN * HH;
    if (idx >= 2 * per) return;
    int hd = idx / per;
    int rem = idx - hd * per;
    int t = rem / HH, j = rem - t * HH;
    const float* gp = g_G + ((size_t)hd * T_LEN + t) * NP + j * 16;
    const float* vp = g_st.v[hd] + j * 16;
    float m = -3.4e38f;
#pragma unroll
    for (int p = 0; p < 16; p++) m = fmaxf(m, gp[p] + vp[p]);
    g_m1[((size_t)hd * T_LEN + t) * HH + j] = m;
}

// ---------------- fused: fc3 GEMM + maxout -> m2 (chunked); fc4 -> alpha; argmax
// smem (floats): m1sT[200][128]=25600 | BsT[200][64]=12800 | w4T[400][16]=6400
//                m2c[128][4]=512 | b4s[16]
#define SC_M1   0
#define SC_B    25600
#define SC_W4   38400
#define SC_M2   44800
#define SC_B4   45312
#define SCORE_SMEM_FLOATS 45328
#define SCORE_SMEM_BYTES  (SCORE_SMEM_FLOATS * 4)

__global__ void __launch_bounds__(256, 1) k_score(
        const float* __restrict__ s4w, const float* __restrict__ s4b,
        const float* __restrict__ e4w, const float* __restrict__ e4b,
        float* __restrict__ out, int iter) {
    extern __shared__ float sm[];
    int hd = blockIdx.y;
    int t0 = blockIdx.x * 128;
    float* outh = out + (size_t)hd * 4 * T_LEN + (size_t)iter * T_LEN;

    if (g_st.done) {       // frozen: alpha[iter] = alpha[iter-1]  (iter >= 2 here)
        for (int t = threadIdx.x; t < 128; t += 256)
            outh[t0 + t] = outh[t0 + t - T_LEN];
        return;
    }

    float* m1sT = sm + SC_M1;   // [200][128]
    float* BsT  = sm + SC_B;    // [200][64]
    float* w4T  = sm + SC_W4;   // [400][16]  w4T[k][p] = w4[p][k]
    float* m2c  = sm + SC_M2;   // [128][4]
    float* b4s  = sm + SC_B4;   // [16]

    int tid = threadIdx.x;
    const float* w4  = hd ? e4w : s4w;
    const float* b4g = hd ? e4b : s4b;
    for (int i = tid; i < 6400; i += 256) {
        int k = i >> 4, p = i & 15;
        w4T[i] = w4[(size_t)p * 400 + k];
    }
    if (tid < 16) b4s[tid] = b4g[tid];

    {   // load m1 block transposed: m1sT[k][m]
        int m = tid & 127, g0 = tid >> 7;
        const float* src = g_m1 + ((size_t)hd * T_LEN + t0 + m) * HH;
        for (int q = g0; q < 50; q += 2) {
            float4 v4 = *(const float4*)(src + q * 4);
            m1sT[(q * 4 + 0) * 128 + m] = v4.x;
            m1sT[(q * 4 + 1) * 128 + m] = v4.y;
            m1sT[(q * 4 + 2) * 128 + m] = v4.z;
            m1sT[(q * 4 + 3) * 128 + m] = v4.w;
        }
    }

    int ty = tid >> 4, tx = tid & 15;   // rows ty*8..+7, cols tx*4..+3
    int row2 = tid >> 1, half = tid & 1;  // fc4 mapping
    float p4[8];                          // fc4 accumulators (8 p's)
#pragma unroll
    for (int i = 0; i < 8; i++) p4[i] = 0.f;

    for (int nc = 0; nc < 50; nc++) {
        int n0 = nc * 64;
        {   // stage w3 chunk transposed: BsT[k][n]
            int n = tid & 63, q0 = tid >> 6;
            const float* src = g_w3 + ((size_t)hd * NP + n0 + n) * 200;
            for (int q = q0; q < 50; q += 4) {
                float4 v4 = *(const float4*)(src + q * 4);
                BsT[(q * 4 + 0) * 64 + n] = v4.x;
                BsT[(q * 4 + 1) * 64 + n] = v4.y;
                BsT[(q * 4 + 2) * 64 + n] = v4.z;
                BsT[(q * 4 + 3) * 64 + n] = v4.w;
            }
        }
        __syncthreads();

        float acc[8][4];
#pragma unroll
        for (int i = 0; i < 8; i++)
#pragma unroll
            for (int j = 0; j < 4; j++) acc[i][j] = 0.f;

#pragma unroll 2
        for (int k = 0; k < 200; k++) {
            float4 a0 = *(const float4*)(m1sT + k * 128 + ty * 8);
            float4 a1 = *(const float4*)(m1sT + k * 128 + ty * 8 + 4);
            float4 bv = *(const float4*)(BsT + k * 64 + tx * 4);
            float av[8] = {a0.x, a0.y, a0.z, a0.w, a1.x, a1.y, a1.z, a1.w};
#pragma unroll
            for (int i = 0; i < 8; i++) {
                acc[i][0] += av[i] * bv.x; acc[i][1] += av[i] * bv.y;
                acc[i][2] += av[i] * bv.z; acc[i][3] += av[i] * bv.w;
            }
        }

        // maxout over 16 cols (4 cols/thread, then shfl over tx-groups of 4)
        float b3v0 = g_b3[hd * NP + n0 + tx * 4 + 0];
        float b3v1 = g_b3[hd * NP + n0 + tx * 4 + 1];
        float b3v2 = g_b3[hd * NP + n0 + tx * 4 + 2];
        float b3v3 = g_b3[hd * NP + n0 + tx * 4 + 3];
#pragma unroll
        for (int i = 0; i < 8; i++) {
            float m = fmaxf(fmaxf(acc[i][0] + b3v0, acc[i][1] + b3v1),
                            fmaxf(acc[i][2] + b3v2, acc[i][3] + b3v3));
            m = fmaxf(m, __shfl_xor_sync(0xffffffffu, m, 1));
            m = fmaxf(m, __shfl_xor_sync(0xffffffffu, m, 2));
            if ((tx & 3) == 0) m2c[(ty * 8 + i) * 4 + (tx >> 2)] = m;
        }
        __syncthreads();

        // fc4 partial: p4[pp] += m2c[row][jl] * w4[p][200 + nc*4 + jl]
        {
            float mv0 = m2c[row2 * 4 + 0], mv1 = m2c[row2 * 4 + 1];
            float mv2 = m2c[row2 * 4 + 2], mv3 = m2c[row2 * 4 + 3];
            const float* w0 = w4T + (200 + nc * 4) * 16 + half * 8;
#pragma unroll
            for (int pp = 0; pp < 8; pp++)
                p4[pp] += mv0 * w0[pp] + mv1 * w0[16 + pp] +
                          mv2 * w0[32 + pp] + mv3 * w0[48 + pp];
        }
        __syncthreads();   // m2c consumed; BsT free for next chunk
    }

    // fc4 m1-part + pool max + output + packed argmax
    {
        for (int k = 0; k < 200; k++) {
            float mval = m1sT[k * 128 + row2];
            const float* wp = w4T + k * 16 + half * 8;
#pragma unroll
            for (int pp = 0; pp < 8; pp++) p4[pp] += mval * wp[pp];
        }
        float v = -3.4e38f;
#pragma unroll
        for (int pp = 0; pp < 8; pp++) v = fmaxf(v, p4[pp] + b4s[half * 8 + pp]);
        v = fmaxf(v, __shfl_xor_sync(0xffffffffu, v, 1));
        if (half == 0) {
            int t = t0 + row2;
            outh[t] = v;
            unsigned key = __float_as_uint(v);
            key = (key & 0x80000000u) ? ~key : (key | 0x80000000u);
            unsigned long long pk =
                ((unsigned long long)key << 32) | (unsigned long long)(0xFFFFFFFFu - (unsigned)t);
            atomicMax(&g_st.amax[hd], pk);
        }
    }
}

// ---------------- argmax decode + done/start/end update ----------------
__global__ void k_update(int iter) {
    if (g_st.done) return;
    unsigned long long a0 = g_st.amax[0], a1 = g_st.amax[1];
    int ns = (int)(0xFFFFFFFFu - (unsigned)(a0 & 0xFFFFFFFFull));
    int ne = (int)(0xFFFFFFFFu - (unsigned)(a1 & 0xFFFFFFFFull));
    if (iter > 0 && ns == g_st.start && ne == g_st.end) g_st.done = 1;
    g_st.start = ns;
    g_st.end = ne;
}

// ---------------- launch ----------------
extern "C" void kernel_launch(void* const* d_in, const int* in_sizes, int n_in,
                              void* d_out, int out_size) {
    const float* U    = (const float*)d_in[0];
    const float* Wih  = (const float*)d_in[1];
    const float* Whh  = (const float*)d_in[2];
    const float* bih  = (const float*)d_in[3];
    const float* bhh  = (const float*)d_in[4];
    const float* s1w  = (const float*)d_in[5];
    const float* s2w  = (const float*)d_in[6];
    const float* s2b  = (const float*)d_in[7];
    const float* s3w  = (const float*)d_in[8];
    const float* s3b  = (const float*)d_in[9];
    const float* s4w  = (const float*)d_in[10];
    const float* s4b  = (const float*)d_in[11];
    const float* e1w  = (const float*)d_in[12];
    const float* e2w  = (const float*)d_in[13];
    const float* e2b  = (const float*)d_in[14];
    const float* e3w  = (const float*)d_in[15];
    const float* e3b  = (const float*)d_in[16];
    const float* e4w  = (const float*)d_in[17];
    const float* e4b  = (const float*)d_in[18];
    float* out = (float*)d_out;

    static int attr_done = 0;
    if (!attr_done) {
        cudaFuncSetAttribute(k_score, cudaFuncAttributeMaxDynamicSharedMemorySize, SCORE_SMEM_BYTES);
        attr_done = 1;
    }

    k_init<<<1, 256>>>();
    k_prep<<<6400, 128>>>(s2w, s2b, s3w, s3b, e2w, e2b, e3w, e3b);

    dim3 gG(NP / 128, T_LEN / 128, 2);
    k_gemm_G<<<gG, 256>>>(U);

    for (int it = 0; it < 4; ++it) {
        k_gates<<<100, 256>>>(U, Wih, Whh, bih, bhh);
        k_act<<<1, 256>>>();
        k_r<<<50, 256>>>(U, s1w, e1w);
        k_v<<<800, 256>>>();
        k_m1<<<(2 * T_LEN * HH + 255) / 256, 256>>>();
        dim3 gs(T_LEN / 128, 2);
        k_score<<<gs, 256, SCORE_SMEM_BYTES>>>(s4w, s4b, e4w, e4b, out, it);
        if (it < 3) k_update<<<1, 1>>>(it);
    }
}

// round 10
// speedup vs baseline: 2.2544x; 1.8248x over previous
#include <cuda_runtime.h>
#include <cuda_bf16.h>
#include <math.h>
#include <stdint.h>

// ---------------- problem constants ----------------
#define T_LEN 16384
#define HH    200
#define NP    3200      // POOL*H

// ---------------- device scratch (static; no allocations allowed) ----------------
__device__ float g_G[2u * T_LEN * NP];        // [hd][t][n'], n' = j*16+p
__device__ float g_m1[2u * T_LEN * HH];       // [hd][t][j]
__device__ float g_w2b[2 * NP * 200];
__device__ float g_b2 [2 * NP];
__device__ float g_b3 [2 * NP];
__device__ float g_gates[800];
// mma B fragments, bf16 hi/lo packed per lane: uint4 = {hi_b0, hi_b1, lo_b0, lo_b1}
__device__ uint4 g_w3f[2 * 50 * 3328];        // [hd][nc50][ks13][nt8][lane32]  (fc3 w)
__device__ uint4 g_w2f[2 * 50 * 25 * 256];    // [hd][nb50][ks25][nt8][lane32]  (fc2a w)
// mma A fragments for U: per (tb,ks): [0..255]=hi plane [mt8][lane32], [256..511]=lo plane
__device__ uint4 g_Uf[128 * 25 * 512];

struct DecState {
    float h[HH];
    float c[HH];
    float r[2][HH];
    float v[2][NP];
    unsigned long long amax[2];
    int start, end, done;
};
__device__ DecState g_st;

// ---------------- helpers ----------------
__device__ __forceinline__ void split_pack(float x0, float x1, uint32_t& hi, uint32_t& lo) {
    __nv_bfloat16 h0 = __float2bfloat16(x0), h1 = __float2bfloat16(x1);
    hi = ((uint32_t)__bfloat16_as_ushort(h1) << 16) | __bfloat16_as_ushort(h0);
    __nv_bfloat16 l0 = __float2bfloat16(x0 - __bfloat162float(h0));
    __nv_bfloat16 l1 = __float2bfloat16(x1 - __bfloat162float(h1));
    lo = ((uint32_t)__bfloat16_as_ushort(l1) << 16) | __bfloat16_as_ushort(l0);
}
__device__ __forceinline__ void mma_bf(float* c, uint4 a, uint32_t b0, uint32_t b1) {
    asm("mma.sync.aligned.m16n8k16.row.col.f32.bf16.bf16.f32 "
        "{%0,%1,%2,%3}, {%4,%5,%6,%7}, {%8,%9}, {%0,%1,%2,%3};\n"
        : "+f"(c[0]), "+f"(c[1]), "+f"(c[2]), "+f"(c[3])
        : "r"(a.x), "r"(a.y), "r"(a.z), "r"(a.w), "r"(b0), "r"(b1));
}

// ---------------- init ----------------
__global__ void k_init() {
    int tid = threadIdx.x;
    for (int j = tid; j < HH; j += blockDim.x) { g_st.h[j] = 0.f; g_st.c[j] = 0.f; }
    if (tid == 0) { g_st.start = 0; g_st.end = 0; g_st.done = 0; }
}

// ---------------- weight reorder + fragment prep ----------
// logical reorder: n' = j*16 + p  <- original fc row p*200+j
__global__ void k_prep(const float* __restrict__ s2w, const float* __restrict__ s2b,
                       const float* __restrict__ s3w, const float* __restrict__ s3b,
                       const float* __restrict__ e2w, const float* __restrict__ e2b,
                       const float* __restrict__ e3w, const float* __restrict__ e3b) {
    int row = blockIdx.x;                 // 0..6399 = hd*NP + n'
    int hd  = row / NP;
    int np  = row - hd * NP;
    int j = np >> 4, p = np & 15;
    int src = p * HH + j;
    const float* w2 = hd ? e2w : s2w;
    const float* b2 = hd ? e2b : s2b;
    const float* w3 = hd ? e3w : s3w;
    const float* b3 = hd ? e3b : s3b;
    const float* w2row = w2 + (size_t)src * 600;
    const float* w3row = w3 + (size_t)src * 200;
    int tid = threadIdx.x;

    for (int k = tid; k < 200; k += 128) g_w2b[(size_t)row * 200 + k] = w2row[400 + k];

    // fc3 B fragments: chunk nc (64 cols), nt, g
    {
        int nc = np >> 6, nl = np & 63, nt = nl >> 3, g = nl & 7;
        uint4* base = g_w3f + (size_t)(hd * 50 + nc) * 3328;
        for (int i = tid; i < 52; i += 128) {
            int ks = i >> 2, tk = i & 3;
            int k0 = ks * 16 + 2 * tk;
            float v0 = w3row[k0], v1 = w3row[k0 + 1];
            float v2 = (k0 + 8 < 200) ? w3row[k0 + 8] : 0.f;
            float v3 = (k0 + 9 < 200) ? w3row[k0 + 9] : 0.f;
            uint4 f;
            split_pack(v0, v1, f.x, f.z);
            split_pack(v2, v3, f.y, f.w);
            base[(ks * 8 + nt) * 32 + 4 * g + tk] = f;
        }
    }
    // fc2a B fragments: tile nb (64 cols)
    {
        int nb = np >> 6, nl = np & 63, nt = nl >> 3, g = nl & 7;
        uint4* base = g_w2f + (size_t)(hd * 50 + nb) * 25 * 256;
        for (int i = tid; i < 100; i += 128) {
            int ks = i >> 2, tk = i & 3;
            int k0 = ks * 16 + 2 * tk;
            float v0 = w2row[k0], v1 = w2row[k0 + 1];
            float v2 = w2row[k0 + 8], v3 = w2row[k0 + 9];
            uint4 f;
            split_pack(v0, v1, f.x, f.z);
            split_pack(v2, v3, f.y, f.w);
            base[ks * 256 + nt * 32 + 4 * g + tk] = f;
        }
    }
    if (tid == 0) { g_b2[row] = b2[src]; g_b3[row] = b3[src]; }
}

// ---------------- U -> A fragments (hi/lo planes) ----------------
__global__ void __launch_bounds__(256) k_splitU(const float* __restrict__ U) {
    int tb = blockIdx.x;
    int tid = threadIdx.x;
    int mt = tid >> 5, lane = tid & 31, g = lane >> 2, tk = lane & 3;
    const float* r0 = U + (size_t)(tb * 128 + mt * 16 + g) * 400;
    const float* r1 = r0 + 8 * 400;
    uint4* dst = g_Uf + (size_t)tb * 25 * 512;
    int fi = mt * 32 + lane;
    for (int ks = 0; ks < 25; ks++) {
        int k0 = ks * 16 + 2 * tk;
        uint4 hi, lo;
        split_pack(r0[k0], r0[k0 + 1], hi.x, lo.x);
        split_pack(r1[k0], r1[k0 + 1], hi.y, lo.y);
        split_pack(r0[k0 + 8], r0[k0 + 9], hi.z, lo.z);
        split_pack(r1[k0 + 8], r1[k0 + 9], hi.w, lo.w);
        dst[ks * 512 + fi] = hi;
        dst[ks * 512 + 256 + fi] = lo;
    }
}

// ---------------- G = U @ w2a^T via mma (128x64 tile/block) ----------------
__global__ void __launch_bounds__(256) k_gemm_G_mma() {
    __shared__ uint4 As[512];   // [0..255]=hi [mt8][lane], [256..511]=lo
    __shared__ uint4 Bs[256];   // [nt8][lane]
    int nb = blockIdx.x, tb = blockIdx.y, hd = blockIdx.z;
    int tid = threadIdx.x, w = tid >> 5, lane = tid & 31;
    int wm = w & 3, wn = w >> 2;          // warp tile: rows 32*wm, cols 32*wn
    int g = lane >> 2, tk = lane & 3;
    float c[2][4][4];
#pragma unroll
    for (int a = 0; a < 2; a++)
#pragma unroll
        for (int b = 0; b < 4; b++)
#pragma unroll
            for (int q = 0; q < 4; q++) c[a][b][q] = 0.f;

    const uint4* Asrc = g_Uf + (size_t)tb * 25 * 512;
    const uint4* Bsrc = g_w2f + (size_t)(hd * 50 + nb) * 25 * 256;

    for (int ks = 0; ks < 25; ks++) {
        __syncthreads();
        for (int i = tid; i < 768; i += 256) {
            if (i < 512) As[i] = Asrc[ks * 512 + i];
            else         Bs[i - 512] = Bsrc[ks * 256 + i - 512];
        }
        __syncthreads();
        uint4 Ah[2], Al[2], Bv[4];
#pragma unroll
        for (int m = 0; m < 2; m++) {
            int mt = wm * 2 + m;
            Ah[m] = As[mt * 32 + lane];
            Al[m] = As[256 + mt * 32 + lane];
        }
#pragma unroll
        for (int n = 0; n < 4; n++) Bv[n] = Bs[(wn * 4 + n) * 32 + lane];
#pragma unroll
        for (int m = 0; m < 2; m++)
#pragma unroll
            for (int n = 0; n < 4; n++) {
                mma_bf(c[m][n], Ah[m], Bv[n].x, Bv[n].y);   // hi*hi
                mma_bf(c[m][n], Ah[m], Bv[n].z, Bv[n].w);   // hi*lo
                mma_bf(c[m][n], Al[m], Bv[n].x, Bv[n].y);   // lo*hi
            }
    }
    // store
#pragma unroll
    for (int m = 0; m < 2; m++) {
#pragma unroll
        for (int h = 0; h < 2; h++) {
            int rrow = tb * 128 + wm * 32 + m * 16 + g + h * 8;
            float* dst = g_G + ((size_t)hd * T_LEN + rrow) * NP + nb * 64 + wn * 32 + tk * 2;
#pragma unroll
            for (int n = 0; n < 4; n++) {
                float2 v;
                v.x = c[m][n][h * 2 + 0];
                v.y = c[m][n][h * 2 + 1];
                *(float2*)(dst + n * 8) = v;
            }
        }
    }
}

// ---------------- LSTM gates: one warp per gate (800 warps) ----------------
__global__ void __launch_bounds__(256) k_gates(const float* __restrict__ U,
        const float* __restrict__ Wih, const float* __restrict__ Whh,
        const float* __restrict__ bih, const float* __restrict__ bhh) {
    if (g_st.done) return;
    int g = blockIdx.x * 8 + (threadIdx.x >> 5);
    int lane = threadIdx.x & 31;
    const float* Us = U + (size_t)g_st.start * 400;
    const float* Ue = U + (size_t)g_st.end * 400;
    const float* wr = Wih + (size_t)g * 800;
    const float* wh = Whh + (size_t)g * HH;
    float acc = 0.f;
#pragma unroll
    for (int q = 0; q < 3; q++) {
        int k = lane * 4 + q * 128;
        float4 w0 = *(const float4*)(wr + k);
        float4 w1 = *(const float4*)(wr + 400 + k);
        float4 x0 = *(const float4*)(Us + k);
        float4 x1 = *(const float4*)(Ue + k);
        acc += w0.x * x0.x + w0.y * x0.y + w0.z * x0.z + w0.w * x0.w;
        acc += w1.x * x1.x + w1.y * x1.y + w1.z * x1.z + w1.w * x1.w;
    }
    {
        int k = 384 + lane * 4;
        if (k < 400) {
            float4 w0 = *(const float4*)(wr + k);
            float4 w1 = *(const float4*)(wr + 400 + k);
            float4 x0 = *(const float4*)(Us + k);
            float4 x1 = *(const float4*)(Ue + k);
            acc += w0.x * x0.x + w0.y * x0.y + w0.z * x0.z + w0.w * x0.w;
            acc += w1.x * x1.x + w1.y * x1.y + w1.z * x1.z + w1.w * x1.w;
        }
    }
    for (int k = lane; k < HH; k += 32) acc += wh[k] * g_st.h[k];
    for (int o = 16; o; o >>= 1) acc += __shfl_xor_sync(0xffffffffu, acc, o);
    if (lane == 0) g_gates[g] = acc + bih[g] + bhh[g];
}

// ---------------- activation + state update ----------------
__global__ void k_act() {
    if (threadIdx.x == 0) { g_st.amax[0] = 0ull; g_st.amax[1] = 0ull; }
    if (g_st.done) return;
    int j = threadIdx.x;
    if (j < HH) {
        float ig = 1.f / (1.f + expf(-g_gates[j]));
        float fg = 1.f / (1.f + expf(-g_gates[200 + j]));
        float gg = tanhf(g_gates[400 + j]);
        float og = 1.f / (1.f + expf(-g_gates[600 + j]));
        float cn = fg * g_st.c[j] + ig * gg;
        g_st.c[j] = cn;
        g_st.h[j] = og * tanhf(cn);
    }
}

// ---------------- r = tanh(fc1w @ [h, U[start], U[end]]) ----------------
__global__ void __launch_bounds__(256) k_r(const float* __restrict__ U,
        const float* __restrict__ s1w, const float* __restrict__ e1w) {
    if (g_st.done) return;
    int idx = blockIdx.x * 8 + (threadIdx.x >> 5);
    int lane = threadIdx.x & 31;
    int hd = idx / HH, j = idx - hd * HH;
    const float* w = (hd ? e1w : s1w) + (size_t)j * 1000;
    const float* Us = U + (size_t)g_st.start * 400;
    const float* Ue = U + (size_t)g_st.end * 400;
    float acc = 0.f;
    for (int k = lane; k < HH; k += 32) acc += w[k] * g_st.h[k];
#pragma unroll
    for (int q = 0; q < 3; q++) {
        int k = lane * 4 + q * 128;
        float4 w0 = *(const float4*)(w + 200 + k);
        float4 w1 = *(const float4*)(w + 600 + k);
        float4 x0 = *(const float4*)(Us + k);
        float4 x1 = *(const float4*)(Ue + k);
        acc += w0.x * x0.x + w0.y * x0.y + w0.z * x0.z + w0.w * x0.w;
        acc += w1.x * x1.x + w1.y * x1.y + w1.z * x1.z + w1.w * x1.w;
    }
    {
        int k = 384 + lane * 4;
        if (k < 400) {
            float4 w0 = *(const float4*)(w + 200 + k);
            float4 w1 = *(const float4*)(w + 600 + k);
            float4 x0 = *(const float4*)(Us + k);
            float4 x1 = *(const float4*)(Ue + k);
            acc += w0.x * x0.x + w0.y * x0.y + w0.z * x0.z + w0.w * x0.w;
            acc += w1.x * x1.x + w1.y * x1.y + w1.z * x1.z + w1.w * x1.w;
        }
    }
    for (int o = 16; o; o >>= 1) acc += __shfl_xor_sync(0xffffffffu, acc, o);
    if (lane == 0) g_st.r[hd][j] = tanhf(acc);
}

// ---------------- v = w2b @ r + b2 ----------------
__global__ void k_v() {
    if (g_st.done) return;
    int gw = (blockIdx.x * blockDim.x + threadIdx.x) >> 5;
    int lane = threadIdx.x & 31;
    if (gw >= 2 * NP) return;
    int hd = gw / NP, n = gw - hd * NP;
    const float* w = g_w2b + ((size_t)hd * NP + n) * 200;
    const float* r = g_st.r[hd];
    float acc = 0.f;
    for (int k = lane; k < 200; k += 32) acc += w[k] * r[k];
    for (int o = 16; o; o >>= 1) acc += __shfl_xor_sync(0xffffffffu, acc, o);
    if (lane == 0) g_st.v[hd][n] = acc + g_b2[hd * NP + n];
}

// ---------------- m1 = maxout_pool(G + v) ----------------
__global__ void k_m1() {
    if (g_st.done) return;
    int idx = blockIdx.x * blockDim.x + threadIdx.x;
    const int per = T_LEN * HH;
    if (idx >= 2 * per) return;
    int hd = idx / per;
    int rem = idx - hd * per;
    int t = rem / HH, j = rem - t * HH;
    const float* gp = g_G + ((size_t)hd * T_LEN + t) * NP + j * 16;
    const float* vp = g_st.v[hd] + j * 16;
    float m = -3.4e38f;
#pragma unroll
    for (int p = 0; p < 16; p++) m = fmaxf(m, gp[p] + vp[p]);
    g_m1[((size_t)hd * T_LEN + t) * HH + j] = m;
}

// ---------------- score: fc3 via mma + maxout + fc4 + argmax ----------------
// smem bytes: AFH 0..53248 | AFL 53248..106496 | BC 106496..159744 |
//             W4 159744..185344 | B3 185344..198144 | B4 198144..198208 | M2 198208..200256
#define SC_AFH 0
#define SC_AFL 53248
#define SC_BC  106496
#define SC_W4  159744
#define SC_B3  185344
#define SC_B4  198144
#define SC_M2  198208
#define SC_SMEM 200256

__global__ void __launch_bounds__(256, 1) k_score_mma(
        const float* __restrict__ s4w, const float* __restrict__ s4b,
        const float* __restrict__ e4w, const float* __restrict__ e4b,
        float* __restrict__ out, int iter) {
    extern __shared__ char smc[];
    int hd = blockIdx.y;
    int t0 = blockIdx.x * 128;
    float* outh = out + (size_t)hd * 4 * T_LEN + (size_t)iter * T_LEN;

    if (g_st.done) {   // frozen: alpha[iter] = alpha[iter-1] (only possible iter>=2)
        for (int t = threadIdx.x; t < 128; t += 256)
            outh[t0 + t] = outh[t0 + t - T_LEN];
        return;
    }

    uint4* AFH = (uint4*)(smc + SC_AFH);
    uint4* AFL = (uint4*)(smc + SC_AFL);
    uint4* BC  = (uint4*)(smc + SC_BC);
    float* w4T = (float*)(smc + SC_W4);
    float* b3s = (float*)(smc + SC_B3);
    float* b4s = (float*)(smc + SC_B4);
    float* m2c = (float*)(smc + SC_M2);

    int tid = threadIdx.x, w = tid >> 5, lane = tid & 31;
    int g = lane >> 2, tk = lane & 3;

    const float* w4 = hd ? e4w : s4w;
    for (int i = tid; i < 6400; i += 256) {
        int k = i >> 4, p = i & 15;
        w4T[i] = w4[(size_t)p * 400 + k];
    }
    for (int i = tid; i < NP; i += 256) b3s[i] = g_b3[hd * NP + i];
    if (tid < 16) b4s[tid] = (hd ? e4b : s4b)[tid];

    // build A fragments from m1 (hi/lo planes)
    {
        int mt = tid >> 5;
        const float* r0 = g_m1 + ((size_t)hd * T_LEN + t0 + mt * 16 + g) * HH;
        const float* r1 = r0 + 8 * HH;
        int fi = mt * 32 + lane;
        for (int ks = 0; ks < 13; ks++) {
            int k0 = ks * 16 + 2 * tk;
            uint4 hi, lo;
            split_pack(r0[k0], r0[k0 + 1], hi.x, lo.x);
            split_pack(r1[k0], r1[k0 + 1], hi.y, lo.y);
            if (k0 + 8 < 200) {
                split_pack(r0[k0 + 8], r0[k0 + 9], hi.z, lo.z);
                split_pack(r1[k0 + 8], r1[k0 + 9], hi.w, lo.w);
            } else { hi.z = hi.w = lo.z = lo.w = 0u; }
            AFH[ks * 256 + fi] = hi;
            AFL[ks * 256 + fi] = lo;
        }
    }
    __syncthreads();

    // fc4 m1-part (thread pair per row)
    int row2 = tid >> 1, half = tid & 1;
    float p4[8];
#pragma unroll
    for (int i = 0; i < 8; i++) p4[i] = 0.f;
    {
        const float* m1row = g_m1 + ((size_t)hd * T_LEN + t0 + row2) * HH;
        for (int k = 0; k < 200; k++) {
            float mv = m1row[k];
            const float* wp = w4T + k * 16 + half * 8;
#pragma unroll
            for (int pp = 0; pp < 8; pp++) p4[pp] += mv * wp[pp];
        }
    }

    int wm = w & 3, wn = w >> 2;   // warp tile: rows 32*wm, cols 32*wn
    const uint4* Bsrc = g_w3f + (size_t)hd * 50 * 3328;

    for (int nc = 0; nc < 50; nc++) {
        // copy B chunk (fragment order, flat)
        for (int i = tid; i < 3328; i += 256) BC[i] = Bsrc[(size_t)nc * 3328 + i];
        __syncthreads();

        float c[2][4][4];
#pragma unroll
        for (int a = 0; a < 2; a++)
#pragma unroll
            for (int b = 0; b < 4; b++)
#pragma unroll
                for (int q = 0; q < 4; q++) c[a][b][q] = 0.f;

        for (int ks = 0; ks < 13; ks++) {
            uint4 Ah[2], Al[2], Bv[4];
#pragma unroll
            for (int m = 0; m < 2; m++) {
                int mt = wm * 2 + m;
                Ah[m] = AFH[ks * 256 + mt * 32 + lane];
                Al[m] = AFL[ks * 256 + mt * 32 + lane];
            }
#pragma unroll
            for (int n = 0; n < 4; n++) Bv[n] = BC[(ks * 8 + wn * 4 + n) * 32 + lane];
#pragma unroll
            for (int m = 0; m < 2; m++)
#pragma unroll
                for (int n = 0; n < 4; n++) {
                    mma_bf(c[m][n], Ah[m], Bv[n].x, Bv[n].y);
                    mma_bf(c[m][n], Ah[m], Bv[n].z, Bv[n].w);
                    mma_bf(c[m][n], Al[m], Bv[n].x, Bv[n].y);
                }
        }

        // maxout (pool 16) -> m2c[128][4]
#pragma unroll
        for (int m = 0; m < 2; m++) {
            int rbase = wm * 32 + m * 16 + g;
#pragma unroll
            for (int grp = 0; grp < 2; grp++) {
                int n0 = grp * 2;
                int colb = nc * 64 + wn * 32 + n0 * 8 + tk * 2;
                float b3a0 = b3s[colb],     b3a1 = b3s[colb + 1];
                float b3b0 = b3s[colb + 8], b3b1 = b3s[colb + 9];
                float vlo = fmaxf(fmaxf(c[m][n0][0] + b3a0, c[m][n0][1] + b3a1),
                                  fmaxf(c[m][n0 + 1][0] + b3b0, c[m][n0 + 1][1] + b3b1));
                float vhi = fmaxf(fmaxf(c[m][n0][2] + b3a0, c[m][n0][3] + b3a1),
                                  fmaxf(c[m][n0 + 1][2] + b3b0, c[m][n0 + 1][3] + b3b1));
                vlo = fmaxf(vlo, __shfl_xor_sync(0xffffffffu, vlo, 1));
                vlo = fmaxf(vlo, __shfl_xor_sync(0xffffffffu, vlo, 2));
                vhi = fmaxf(vhi, __shfl_xor_sync(0xffffffffu, vhi, 1));
                vhi = fmaxf(vhi, __shfl_xor_sync(0xffffffffu, vhi, 2));
                if (tk == 0) {
                    m2c[rbase * 4 + wn * 2 + grp] = vlo;
                    m2c[(rbase + 8) * 4 + wn * 2 + grp] = vhi;
                }
            }
        }
        __syncthreads();

        // fc4 partial from this chunk's 4 pooled values
        {
            float mv0 = m2c[row2 * 4 + 0], mv1 = m2c[row2 * 4 + 1];
            float mv2 = m2c[row2 * 4 + 2], mv3 = m2c[row2 * 4 + 3];
            const float* w0 = w4T + (200 + nc * 4) * 16 + half * 8;
#pragma unroll
            for (int pp = 0; pp < 8; pp++)
                p4[pp] += mv0 * w0[pp] + mv1 * w0[16 + pp] +
                          mv2 * w0[32 + pp] + mv3 * w0[48 + pp];
        }
        __syncthreads();
    }

    // final: pool-max over fc4, write alpha, warp-reduced packed argmax
    {
        float v = p4[0] + b4s[half * 8];
#pragma unroll
        for (int pp = 1; pp < 8; pp++) v = fmaxf(v, p4[pp] + b4s[half * 8 + pp]);
        v = fmaxf(v, __shfl_xor_sync(0xffffffffu, v, 1));
        if (half == 0) outh[t0 + row2] = v;
        int trow = t0 + row2;
        unsigned key = __float_as_uint(v);
        key = (key & 0x80000000u) ? ~key : (key | 0x80000000u);
        unsigned long long pk =
            ((unsigned long long)key << 32) | (unsigned long long)(0xFFFFFFFFu - (unsigned)trow);
#pragma unroll
        for (int o = 16; o; o >>= 1) {
            unsigned long long other = __shfl_xor_sync(0xffffffffu, pk, o);
            if (other > pk) pk = other;
        }
        if (lane == 0) atomicMax(&g_st.amax[hd], pk);
    }
}

// ---------------- argmax decode + done/start/end update ----------------
__global__ void k_update(int iter) {
    if (g_st.done) return;
    unsigned long long a0 = g_st.amax[0], a1 = g_st.amax[1];
    int ns = (int)(0xFFFFFFFFu - (unsigned)(a0 & 0xFFFFFFFFull));
    int ne = (int)(0xFFFFFFFFu - (unsigned)(a1 & 0xFFFFFFFFull));
    if (iter > 0 && ns == g_st.start && ne == g_st.end) g_st.done = 1;
    g_st.start = ns;
    g_st.end = ne;
}

// ---------------- launch ----------------
extern "C" void kernel_launch(void* const* d_in, const int* in_sizes, int n_in,
                              void* d_out, int out_size) {
    const float* U    = (const float*)d_in[0];
    const float* Wih  = (const float*)d_in[1];
    const float* Whh  = (const float*)d_in[2];
    const float* bih  = (const float*)d_in[3];
    const float* bhh  = (const float*)d_in[4];
    const float* s1w  = (const float*)d_in[5];
    const float* s2w  = (const float*)d_in[6];
    const float* s2b  = (const float*)d_in[7];
    const float* s3w  = (const float*)d_in[8];
    const float* s3b  = (const float*)d_in[9];
    const float* s4w  = (const float*)d_in[10];
    const float* s4b  = (const float*)d_in[11];
    const float* e1w  = (const float*)d_in[12];
    const float* e2w  = (const float*)d_in[13];
    const float* e2b  = (const float*)d_in[14];
    const float* e3w  = (const float*)d_in[15];
    const float* e3b  = (const float*)d_in[16];
    const float* e4w  = (const float*)d_in[17];
    const float* e4b  = (const float*)d_in[18];
    float* out = (float*)d_out;

    cudaFuncSetAttribute(k_score_mma, cudaFuncAttributeMaxDynamicSharedMemorySize, SC_SMEM);

    k_init<<<1, 256>>>();
    k_prep<<<6400, 128>>>(s2w, s2b, s3w, s3b, e2w, e2b, e3w, e3b);
    k_splitU<<<128, 256>>>(U);

    dim3 gG(50, 128, 2);
    k_gemm_G_mma<<<gG, 256>>>();

    for (int it = 0; it < 4; ++it) {
        k_gates<<<100, 256>>>(U, Wih, Whh, bih, bhh);
        k_act<<<1, 256>>>();
        k_r<<<50, 256>>>(U, s1w, e1w);
        k_v<<<800, 256>>>();
        k_m1<<<(2 * T_LEN * HH + 255) / 256, 256>>>();
        dim3 gs(T_LEN / 128, 2);
        k_score_mma<<<gs, 256, SC_SMEM>>>(s4w, s4b, e4w, e4b, out, it);
        if (it < 3) k_update<<<1, 1>>>(it);
    }
}

// round 12
// speedup vs baseline: 2.3716x; 1.0520x over previous
#include <cuda_runtime.h>
#include <cuda_bf16.h>
#include <math.h>
#include <stdint.h>

// ---------------- problem constants ----------------
#define T_LEN 16384
#define HH    200
#define NP    3200      // POOL*H

// ---------------- device scratch (static; no allocations allowed) ----------------
__device__ float g_G[2u * T_LEN * NP];        // [hd][t][n'], n' = j*16+p
__device__ float g_w2b[2 * NP * 200];
__device__ float g_b2 [2 * NP];
__device__ float g_b3 [2 * NP];
__device__ float g_gates[800];
// mma B fragments, bf16 hi/lo packed per lane: uint4 = {hi_b0, hi_b1, lo_b0, lo_b1}
__device__ uint4 g_w3f[2 * 50 * 3328];        // [hd][nc50][ks13][nt8][lane32]  (fc3 w)
__device__ uint4 g_w2f[2 * 50 * 25 * 256];    // [hd][nb50][ks25][nt8][lane32]  (fc2a w)
// mma A fragments for U: per (tb,ks): [0..255]=hi plane [mt8][lane32], [256..511]=lo plane
__device__ uint4 g_Uf[128 * 25 * 512];

struct DecState {
    float h[HH];
    float c[HH];
    float r[2][HH];
    float v[2][NP];
    unsigned long long amax[2];
    int start, end, done;
};
__device__ DecState g_st;

// ---------------- helpers ----------------
__device__ __forceinline__ void split_pack(float x0, float x1, uint32_t& hi, uint32_t& lo) {
    __nv_bfloat16 h0 = __float2bfloat16(x0), h1 = __float2bfloat16(x1);
    hi = ((uint32_t)__bfloat16_as_ushort(h1) << 16) | __bfloat16_as_ushort(h0);
    __nv_bfloat16 l0 = __float2bfloat16(x0 - __bfloat162float(h0));
    __nv_bfloat16 l1 = __float2bfloat16(x1 - __bfloat162float(h1));
    lo = ((uint32_t)__bfloat16_as_ushort(l1) << 16) | __bfloat16_as_ushort(l0);
}
__device__ __forceinline__ void mma_bf(float* c, uint4 a, uint32_t b0, uint32_t b1) {
    asm("mma.sync.aligned.m16n8k16.row.col.f32.bf16.bf16.f32 "
        "{%0,%1,%2,%3}, {%4,%5,%6,%7}, {%8,%9}, {%0,%1,%2,%3};\n"
        : "+f"(c[0]), "+f"(c[1]), "+f"(c[2]), "+f"(c[3])
        : "r"(a.x), "r"(a.y), "r"(a.z), "r"(a.w), "r"(b0), "r"(b1));
}
// pool-16 maxout of G row segment + v segment
__device__ __forceinline__ float maxout16(const float* gp, const float* vp) {
    float m = -3.4e38f;
#pragma unroll
    for (int q = 0; q < 4; q++) {
        float4 gg = *(const float4*)(gp + q * 4);
        float4 vv = *(const float4*)(vp + q * 4);
        m = fmaxf(m, fmaxf(fmaxf(gg.x + vv.x, gg.y + vv.y), fmaxf(gg.z + vv.z, gg.w + vv.w)));
    }
    return m;
}
__device__ __forceinline__ float bf_lo(uint32_t u) {
    return __bfloat162float(__ushort_as_bfloat16((unsigned short)(u & 0xFFFF)));
}
__device__ __forceinline__ float bf_hi(uint32_t u) {
    return __bfloat162float(__ushort_as_bfloat16((unsigned short)(u >> 16)));
}

// ---------------- init ----------------
__global__ void k_init() {
    int tid = threadIdx.x;
    for (int j = tid; j < HH; j += blockDim.x) { g_st.h[j] = 0.f; g_st.c[j] = 0.f; }
    if (tid == 0) { g_st.start = 0; g_st.end = 0; g_st.done = 0; }
}

// ---------------- weight reorder + fragment prep ----------
__global__ void k_prep(const float* __restrict__ s2w, const float* __restrict__ s2b,
                       const float* __restrict__ s3w, const float* __restrict__ s3b,
                       const float* __restrict__ e2w, const float* __restrict__ e2b,
                       const float* __restrict__ e3w, const float* __restrict__ e3b) {
    int row = blockIdx.x;                 // 0..6399 = hd*NP + n'
    int hd  = row / NP;
    int np  = row - hd * NP;
    int j = np >> 4, p = np & 15;
    int src = p * HH + j;
    const float* w2 = hd ? e2w : s2w;
    const float* b2 = hd ? e2b : s2b;
    const float* w3 = hd ? e3w : s3w;
    const float* b3 = hd ? e3b : s3b;
    const float* w2row = w2 + (size_t)src * 600;
    const float* w3row = w3 + (size_t)src * 200;
    int tid = threadIdx.x;

    for (int k = tid; k < 200; k += 128) g_w2b[(size_t)row * 200 + k] = w2row[400 + k];

    {   // fc3 B fragments
        int nc = np >> 6, nl = np & 63, nt = nl >> 3, g = nl & 7;
        uint4* base = g_w3f + (size_t)(hd * 50 + nc) * 3328;
        for (int i = tid; i < 52; i += 128) {
            int ks = i >> 2, tk = i & 3;
            int k0 = ks * 16 + 2 * tk;
            float v0 = w3row[k0], v1 = w3row[k0 + 1];
            float v2 = (k0 + 8 < 200) ? w3row[k0 + 8] : 0.f;
            float v3 = (k0 + 9 < 200) ? w3row[k0 + 9] : 0.f;
            uint4 f;
            split_pack(v0, v1, f.x, f.z);
            split_pack(v2, v3, f.y, f.w);
            base[(ks * 8 + nt) * 32 + 4 * g + tk] = f;
        }
    }
    {   // fc2a B fragments
        int nb = np >> 6, nl = np & 63, nt = nl >> 3, g = nl & 7;
        uint4* base = g_w2f + (size_t)(hd * 50 + nb) * 25 * 256;
        for (int i = tid; i < 100; i += 128) {
            int ks = i >> 2, tk = i & 3;
            int k0 = ks * 16 + 2 * tk;
            uint4 f;
            split_pack(w2row[k0], w2row[k0 + 1], f.x, f.z);
            split_pack(w2row[k0 + 8], w2row[k0 + 9], f.y, f.w);
            base[ks * 256 + nt * 32 + 4 * g + tk] = f;
        }
    }
    if (tid == 0) { g_b2[row] = b2[src]; g_b3[row] = b3[src]; }
}

// ---------------- U -> A fragments (hi/lo planes) ----------------
__global__ void __launch_bounds__(256) k_splitU(const float* __restrict__ U) {
    int tb = blockIdx.x;
    int tid = threadIdx.x;
    int mt = tid >> 5, lane = tid & 31, g = lane >> 2, tk = lane & 3;
    const float* r0 = U + (size_t)(tb * 128 + mt * 16 + g) * 400;
    const float* r1 = r0 + 8 * 400;
    uint4* dst = g_Uf + (size_t)tb * 25 * 512;
    int fi = mt * 32 + lane;
    for (int ks = 0; ks < 25; ks++) {
        int k0 = ks * 16 + 2 * tk;
        uint4 hi, lo;
        split_pack(r0[k0], r0[k0 + 1], hi.x, lo.x);
        split_pack(r1[k0], r1[k0 + 1], hi.y, lo.y);
        split_pack(r0[k0 + 8], r0[k0 + 9], hi.z, lo.z);
        split_pack(r1[k0 + 8], r1[k0 + 9], hi.w, lo.w);
        dst[ks * 512 + fi] = hi;
        dst[ks * 512 + 256 + fi] = lo;
    }
}

// ---------------- G = U @ w2a^T via mma (128x64 tile/block, reg-prefetch) -------
__global__ void __launch_bounds__(256) k_gemm_G_mma() {
    __shared__ uint4 As[512];
    __shared__ uint4 Bs[256];
    int nb = blockIdx.x, tb = blockIdx.y, hd = blockIdx.z;
    int tid = threadIdx.x, w = tid >> 5, lane = tid & 31;
    int wm = w & 3, wn = w >> 2;
    int g = lane >> 2, tk = lane & 3;
    float c[2][4][4];
#pragma unroll
    for (int a = 0; a < 2; a++)
#pragma unroll
        for (int b = 0; b < 4; b++)
#pragma unroll
            for (int q = 0; q < 4; q++) c[a][b][q] = 0.f;

    const uint4* Asrc = g_Uf + (size_t)tb * 25 * 512;
    const uint4* Bsrc = g_w2f + (size_t)(hd * 50 + nb) * 25 * 256;

    uint4 r0 = Asrc[tid], r1 = Asrc[256 + tid], r2 = Bsrc[tid];
    for (int ks = 0; ks < 25; ks++) {
        __syncthreads();
        As[tid] = r0; As[256 + tid] = r1; Bs[tid] = r2;
        __syncthreads();
        if (ks + 1 < 25) {
            r0 = Asrc[(ks + 1) * 512 + tid];
            r1 = Asrc[(ks + 1) * 512 + 256 + tid];
            r2 = Bsrc[(ks + 1) * 256 + tid];
        }
        uint4 Ah[2], Al[2], Bv[4];
#pragma unroll
        for (int m = 0; m < 2; m++) {
            int mt = wm * 2 + m;
            Ah[m] = As[mt * 32 + lane];
            Al[m] = As[256 + mt * 32 + lane];
        }
#pragma unroll
        for (int n = 0; n < 4; n++) Bv[n] = Bs[(wn * 4 + n) * 32 + lane];
#pragma unroll
        for (int m = 0; m < 2; m++)
#pragma unroll
            for (int n = 0; n < 4; n++) {
                mma_bf(c[m][n], Ah[m], Bv[n].x, Bv[n].y);
                mma_bf(c[m][n], Ah[m], Bv[n].z, Bv[n].w);
                mma_bf(c[m][n], Al[m], Bv[n].x, Bv[n].y);
            }
    }
#pragma unroll
    for (int m = 0; m < 2; m++) {
#pragma unroll
        for (int h = 0; h < 2; h++) {
            int rrow = tb * 128 + wm * 32 + m * 16 + g + h * 8;
            float* dst = g_G + ((size_t)hd * T_LEN + rrow) * NP + nb * 64 + wn * 32 + tk * 2;
#pragma unroll
            for (int n = 0; n < 4; n++) {
                float2 v;
                v.x = c[m][n][h * 2 + 0];
                v.y = c[m][n][h * 2 + 1];
                *(float2*)(dst + n * 8) = v;
            }
        }
    }
}

// ---------------- LSTM gates ----------------
__global__ void __launch_bounds__(256) k_gates(const float* __restrict__ U,
        const float* __restrict__ Wih, const float* __restrict__ Whh,
        const float* __restrict__ bih, const float* __restrict__ bhh) {
    if (g_st.done) return;
    int g = blockIdx.x * 8 + (threadIdx.x >> 5);
    int lane = threadIdx.x & 31;
    const float* Us = U + (size_t)g_st.start * 400;
    const float* Ue = U + (size_t)g_st.end * 400;
    const float* wr = Wih + (size_t)g * 800;
    const float* wh = Whh + (size_t)g * HH;
    float acc = 0.f;
#pragma unroll
    for (int q = 0; q < 3; q++) {
        int k = lane * 4 + q * 128;
        float4 w0 = *(const float4*)(wr + k);
        float4 w1 = *(const float4*)(wr + 400 + k);
        float4 x0 = *(const float4*)(Us + k);
        float4 x1 = *(const float4*)(Ue + k);
        acc += w0.x * x0.x + w0.y * x0.y + w0.z * x0.z + w0.w * x0.w;
        acc += w1.x * x1.x + w1.y * x1.y + w1.z * x1.z + w1.w * x1.w;
    }
    {
        int k = 384 + lane * 4;
        if (k < 400) {
            float4 w0 = *(const float4*)(wr + k);
            float4 w1 = *(const float4*)(wr + 400 + k);
            float4 x0 = *(const float4*)(Us + k);
            float4 x1 = *(const float4*)(Ue + k);
            acc += w0.x * x0.x + w0.y * x0.y + w0.z * x0.z + w0.w * x0.w;
            acc += w1.x * x1.x + w1.y * x1.y + w1.z * x1.z + w1.w * x1.w;
        }
    }
    for (int k = lane; k < HH; k += 32) acc += wh[k] * g_st.h[k];
    for (int o = 16; o; o >>= 1) acc += __shfl_xor_sync(0xffffffffu, acc, o);
    if (lane == 0) g_gates[g] = acc + bih[g] + bhh[g];
}

// ---------------- activation + state update ----------------
__global__ void k_act() {
    if (threadIdx.x == 0) { g_st.amax[0] = 0ull; g_st.amax[1] = 0ull; }
    if (g_st.done) return;
    int j = threadIdx.x;
    if (j < HH) {
        float ig = 1.f / (1.f + expf(-g_gates[j]));
        float fg = 1.f / (1.f + expf(-g_gates[200 + j]));
        float gg = tanhf(g_gates[400 + j]);
        float og = 1.f / (1.f + expf(-g_gates[600 + j]));
        float cn = fg * g_st.c[j] + ig * gg;
        g_st.c[j] = cn;
        g_st.h[j] = og * tanhf(cn);
    }
}

// ---------------- r = tanh(fc1w @ [h, U[start], U[end]]) ----------------
__global__ void __launch_bounds__(256) k_r(const float* __restrict__ U,
        const float* __restrict__ s1w, const float* __restrict__ e1w) {
    if (g_st.done) return;
    int idx = blockIdx.x * 8 + (threadIdx.x >> 5);
    int lane = threadIdx.x & 31;
    int hd = idx / HH, j = idx - hd * HH;
    const float* w = (hd ? e1w : s1w) + (size_t)j * 1000;
    const float* Us = U + (size_t)g_st.start * 400;
    const float* Ue = U + (size_t)g_st.end * 400;
    float acc = 0.f;
    for (int k = lane; k < HH; k += 32) acc += w[k] * g_st.h[k];
#pragma unroll
    for (int q = 0; q < 3; q++) {
        int k = lane * 4 + q * 128;
        float4 w0 = *(const float4*)(w + 200 + k);
        float4 w1 = *(const float4*)(w + 600 + k);
        float4 x0 = *(const float4*)(Us + k);
        float4 x1 = *(const float4*)(Ue + k);
        acc += w0.x * x0.x + w0.y * x0.y + w0.z * x0.z + w0.w * x0.w;
        acc += w1.x * x1.x + w1.y * x1.y + w1.z * x1.z + w1.w * x1.w;
    }
    {
        int k = 384 + lane * 4;
        if (k < 400) {
            float4 w0 = *(const float4*)(w + 200 + k);
            float4 w1 = *(const float4*)(w + 600 + k);
            float4 x0 = *(const float4*)(Us + k);
            float4 x1 = *(const float4*)(Ue + k);
            acc += w0.x * x0.x + w0.y * x0.y + w0.z * x0.z + w0.w * x0.w;
            acc += w1.x * x1.x + w1.y * x1.y + w1.z * x1.z + w1.w * x1.w;
        }
    }
    for (int o = 16; o; o >>= 1) acc += __shfl_xor_sync(0xffffffffu, acc, o);
    if (lane == 0) g_st.r[hd][j] = tanhf(acc);
}

// ---------------- v = w2b @ r + b2 ----------------
__global__ void k_v() {
    if (g_st.done) return;
    int gw = (blockIdx.x * blockDim.x + threadIdx.x) >> 5;
    int lane = threadIdx.x & 31;
    if (gw >= 2 * NP) return;
    int hd = gw / NP, n = gw - hd * NP;
    const float* w = g_w2b + ((size_t)hd * NP + n) * 200;
    const float* r = g_st.r[hd];
    float acc = 0.f;
    for (int k = lane; k < 200; k += 32) acc += w[k] * r[k];
    for (int o = 16; o; o >>= 1) acc += __shfl_xor_sync(0xffffffffu, acc, o);
    if (lane == 0) g_st.v[hd][n] = acc + g_b2[hd * NP + n];
}

// ---------------- score: fused maxout(G+v) + fc3 mma + maxout + fc4 + argmax ----
// smem bytes:
#define SC_AFH 0
#define SC_AFL 53248
#define SC_BC  106496
#define SC_W4  159744
#define SC_B3  185344
#define SC_VS  198144
#define SC_B4  210944
#define SC_M2  211008
#define SC_SMEM 213056

__global__ void __launch_bounds__(512, 1) k_score_mma(
        const float* __restrict__ s4w, const float* __restrict__ s4b,
        const float* __restrict__ e4w, const float* __restrict__ e4b,
        float* __restrict__ out, int iter) {
    extern __shared__ char smc[];
    int hd = blockIdx.y;
    int t0 = blockIdx.x * 128;
    float* outh = out + (size_t)hd * 4 * T_LEN + (size_t)iter * T_LEN;

    if (g_st.done) {   // frozen: alpha[iter] = alpha[iter-1] (only possible iter>=2)
        for (int t = threadIdx.x; t < 128; t += 512)
            outh[t0 + t] = outh[t0 + t - T_LEN];
        return;
    }

    uint4* AFH = (uint4*)(smc + SC_AFH);
    uint4* AFL = (uint4*)(smc + SC_AFL);
    uint4* BC  = (uint4*)(smc + SC_BC);
    float* w4T = (float*)(smc + SC_W4);
    float* b3s = (float*)(smc + SC_B3);
    float* vs  = (float*)(smc + SC_VS);
    float* b4s = (float*)(smc + SC_B4);
    float* m2c = (float*)(smc + SC_M2);

    int tid = threadIdx.x, w = tid >> 5, lane = tid & 31;
    int g = lane >> 2, tk = lane & 3;

    const float* w4 = hd ? e4w : s4w;
    for (int i = tid; i < 6400; i += 512) {
        int k = i >> 4, p = i & 15;
        w4T[i] = w4[(size_t)p * 400 + k];
    }
    for (int i = tid; i < NP; i += 512) {
        b3s[i] = g_b3[hd * NP + i];
        vs[i]  = g_st.v[hd][i];
    }
    if (tid < 16) b4s[tid] = (hd ? e4b : s4b)[tid];
    __syncthreads();

    // ---- A-build: fused pool-16 maxout of (G + v), split to bf16 hi/lo fragments
    {
        int mt = w & 7;
        int ksb = (w >> 3) ? 7 : 0;
        int kse = (w >> 3) ? 13 : 7;
        const float* gr0 = g_G + ((size_t)hd * T_LEN + t0 + mt * 16 + g) * NP;
        const float* gr1 = gr0 + (size_t)8 * NP;
        int fi = mt * 32 + lane;
        for (int ks = ksb; ks < kse; ks++) {
            int k0 = ks * 16 + 2 * tk;
            uint4 hi, lo;
            float a0 = maxout16(gr0 + (size_t)k0 * 16, vs + k0 * 16);
            float a1 = maxout16(gr0 + (size_t)(k0 + 1) * 16, vs + (k0 + 1) * 16);
            float b0 = maxout16(gr1 + (size_t)k0 * 16, vs + k0 * 16);
            float b1 = maxout16(gr1 + (size_t)(k0 + 1) * 16, vs + (k0 + 1) * 16);
            split_pack(a0, a1, hi.x, lo.x);
            split_pack(b0, b1, hi.y, lo.y);
            if (k0 + 8 < 200) {
                float a2 = maxout16(gr0 + (size_t)(k0 + 8) * 16, vs + (k0 + 8) * 16);
                float a3 = maxout16(gr0 + (size_t)(k0 + 9) * 16, vs + (k0 + 9) * 16);
                float b2 = maxout16(gr1 + (size_t)(k0 + 8) * 16, vs + (k0 + 8) * 16);
                float b3v = maxout16(gr1 + (size_t)(k0 + 9) * 16, vs + (k0 + 9) * 16);
                split_pack(a2, a3, hi.z, lo.z);
                split_pack(b2, b3v, hi.w, lo.w);
            } else { hi.z = hi.w = lo.z = lo.w = 0u; }
            AFH[ks * 256 + fi] = hi;
            AFL[ks * 256 + fi] = lo;
        }
    }
    __syncthreads();

    // ---- fc4 m1-part: reconstruct m1 = hi + lo from fragments ----
    int row4 = tid >> 2, q4 = tid & 3;       // 4 threads per row, 4 p's each
    float p4[4];
#pragma unroll
    for (int i = 0; i < 4; i++) p4[i] = 0.f;
    {
        int mt = row4 >> 4, rem = row4 & 15, h = rem >> 3, gr = rem & 7;
        for (int ks = 0; ks < 13; ks++) {
#pragma unroll
            for (int tkk = 0; tkk < 4; tkk++) {
                int idx = ks * 256 + mt * 32 + gr * 4 + tkk;
                uint4 H = AFH[idx], L = AFL[idx];
                uint32_t ua = h ? H.y : H.x, la = h ? L.y : L.x;
                uint32_t ub = h ? H.w : H.z, lb = h ? L.w : L.z;
                int k0 = ks * 16 + 2 * tkk;
                float m0 = bf_lo(ua) + bf_lo(la);
                float m1v = bf_hi(ua) + bf_hi(la);
                const float* wp0 = w4T + k0 * 16 + q4 * 4;
#pragma unroll
                for (int pp = 0; pp < 4; pp++)
                    p4[pp] += m0 * wp0[pp] + m1v * wp0[16 + pp];
                if (k0 + 8 < 200) {
                    float m2 = bf_lo(ub) + bf_lo(lb);
                    float m3 = bf_hi(ub) + bf_hi(lb);
                    const float* wp8 = w4T + (k0 + 8) * 16 + q4 * 4;
#pragma unroll
                    for (int pp = 0; pp < 4; pp++)
                        p4[pp] += m2 * wp8[pp] + m3 * wp8[16 + pp];
                }
            }
        }
    }

    int wm = w & 7, wn = w >> 3;   // warp tile: rows 16*wm, cols 32*wn
    const uint4* Bsrc = g_w3f + (size_t)hd * 50 * 3328;

    for (int nc = 0; nc < 50; nc++) {
        for (int i = tid; i < 3328; i += 512) BC[i] = Bsrc[(size_t)nc * 3328 + i];
        __syncthreads();

        float c[4][4];
#pragma unroll
        for (int b = 0; b < 4; b++)
#pragma unroll
            for (int qq = 0; qq < 4; qq++) c[b][qq] = 0.f;

        for (int ks = 0; ks < 13; ks++) {
            uint4 Ah = AFH[ks * 256 + wm * 32 + lane];
            uint4 Al = AFL[ks * 256 + wm * 32 + lane];
            uint4 Bv[4];
#pragma unroll
            for (int n = 0; n < 4; n++) Bv[n] = BC[(ks * 8 + wn * 4 + n) * 32 + lane];
#pragma unroll
            for (int n = 0; n < 4; n++) {
                mma_bf(c[n], Ah, Bv[n].x, Bv[n].y);
                mma_bf(c[n], Ah, Bv[n].z, Bv[n].w);
                mma_bf(c[n], Al, Bv[n].x, Bv[n].y);
            }
        }

        // maxout (pool 16) -> m2c[128][4]
        {
            int rloc = wm * 16 + g;
#pragma unroll
            for (int grp = 0; grp < 2; grp++) {
                int n0 = grp * 2;
                int colb = nc * 64 + wn * 32 + grp * 16 + tk * 2;
                float b3a0 = b3s[colb],     b3a1 = b3s[colb + 1];
                float b3b0 = b3s[colb + 8], b3b1 = b3s[colb + 9];
                float vlo = fmaxf(fmaxf(c[n0][0] + b3a0, c[n0][1] + b3a1),
                                  fmaxf(c[n0 + 1][0] + b3b0, c[n0 + 1][1] + b3b1));
                float vhi = fmaxf(fmaxf(c[n0][2] + b3a0, c[n0][3] + b3a1),
                                  fmaxf(c[n0 + 1][2] + b3b0, c[n0 + 1][3] + b3b1));
                vlo = fmaxf(vlo, __shfl_xor_sync(0xffffffffu, vlo, 1));
                vlo = fmaxf(vlo, __shfl_xor_sync(0xffffffffu, vlo, 2));
                vhi = fmaxf(vhi, __shfl_xor_sync(0xffffffffu, vhi, 1));
                vhi = fmaxf(vhi, __shfl_xor_sync(0xffffffffu, vhi, 2));
                if (tk == 0) {
                    m2c[rloc * 4 + wn * 2 + grp] = vlo;
                    m2c[(rloc + 8) * 4 + wn * 2 + grp] = vhi;
                }
            }
        }
        __syncthreads();

        // fc4 partial from this chunk's 4 pooled values
        {
            float mv0 = m2c[row4 * 4 + 0], mv1 = m2c[row4 * 4 + 1];
            float mv2 = m2c[row4 * 4 + 2], mv3 = m2c[row4 * 4 + 3];
            const float* w0 = w4T + (200 + nc * 4) * 16 + q4 * 4;
#pragma unroll
            for (int pp = 0; pp < 4; pp++)
                p4[pp] += mv0 * w0[pp] + mv1 * w0[16 + pp] +
                          mv2 * w0[32 + pp] + mv3 * w0[48 + pp];
        }
        __syncthreads();
    }

    // ---- final: pool-max over fc4, write alpha, warp-reduced packed argmax ----
    {
        float v = p4[0] + b4s[q4 * 4];
#pragma unroll
        for (int pp = 1; pp < 4; pp++) v = fmaxf(v, p4[pp] + b4s[q4 * 4 + pp]);
        v = fmaxf(v, __shfl_xor_sync(0xffffffffu, v, 1));
        v = fmaxf(v, __shfl_xor_sync(0xffffffffu, v, 2));
        if (q4 == 0) outh[t0 + row4] = v;
        int trow = t0 + row4;
        unsigned key = __float_as_uint(v);
        key = (key & 0x80000000u) ? ~key : (key | 0x80000000u);
        unsigned long long pk =
            ((unsigned long long)key << 32) | (unsigned long long)(0xFFFFFFFFu - (unsigned)trow);
#pragma unroll
        for (int o = 16; o; o >>= 1) {
            unsigned long long other = __shfl_xor_sync(0xffffffffu, pk, o);
            if (other > pk) pk = other;
        }
        if (lane == 0) atomicMax(&g_st.amax[hd], pk);
    }
}

// ---------------- argmax decode + done/start/end update ----------------
__global__ void k_update(int iter) {
    if (g_st.done) return;
    unsigned long long a0 = g_st.amax[0], a1 = g_st.amax[1];
    int ns = (int)(0xFFFFFFFFu - (unsigned)(a0 & 0xFFFFFFFFull));
    int ne = (int)(0xFFFFFFFFu - (unsigned)(a1 & 0xFFFFFFFFull));
    if (iter > 0 && ns == g_st.start && ne == g_st.end) g_st.done = 1;
    g_st.start = ns;
    g_st.end = ne;
}

// ---------------- launch ----------------
extern "C" void kernel_launch(void* const* d_in, const int* in_sizes, int n_in,
                              void* d_out, int out_size) {
    const float* U    = (const float*)d_in[0];
    const float* Wih  = (const float*)d_in[1];
    const float* Whh  = (const float*)d_in[2];
    const float* bih  = (const float*)d_in[3];
    const float* bhh  = (const float*)d_in[4];
    const float* s1w  = (const float*)d_in[5];
    const float* s2w  = (const float*)d_in[6];
    const float* s2b  = (const float*)d_in[7];
    const float* s3w  = (const float*)d_in[8];
    const float* s3b  = (const float*)d_in[9];
    const float* s4w  = (const float*)d_in[10];
    const float* s4b  = (const float*)d_in[11];
    const float* e1w  = (const float*)d_in[12];
    const float* e2w  = (const float*)d_in[13];
    const float* e2b  = (const float*)d_in[14];
    const float* e3w  = (const float*)d_in[15];
    const float* e3b  = (const float*)d_in[16];
    const float* e4w  = (const float*)d_in[17];
    const float* e4b  = (const float*)d_in[18];
    float* out = (float*)d_out;

    cudaFuncSetAttribute(k_score_mma, cudaFuncAttributeMaxDynamicSharedMemorySize, SC_SMEM);

    k_init<<<1, 256>>>();
    k_prep<<<6400, 128>>>(s2w, s2b, s3w, s3b, e2w, e2b, e3w, e3b);
    k_splitU<<<128, 256>>>(U);

    dim3 gG(50, 128, 2);
    k_gemm_G_mma<<<gG, 256>>>();

    for (int it = 0; it < 4; ++it) {
        k_gates<<<100, 256>>>(U, Wih, Whh, bih, bhh);
        k_act<<<1, 256>>>();
        k_r<<<50, 256>>>(U, s1w, e1w);
        k_v<<<800, 256>>>();
        dim3 gs(T_LEN / 128, 2);
        k_score_mma<<<gs, 512, SC_SMEM>>>(s4w, s4b, e4w, e4b, out, it);
        if (it < 3) k_update<<<1, 1>>>(it);
    }
}

// round 13
// speedup vs baseline: 3.0395x; 1.2816x over previous
#include <cuda_runtime.h>
#include <cuda_bf16.h>
#include <math.h>
#include <stdint.h>

// ---------------- problem constants ----------------
#define T_LEN 16384
#define HH    200
#define NP    3200      // POOL*H

// ---------------- device scratch (static; no allocations allowed) ----------------
__device__ float g_G[2u * T_LEN * NP];        // [hd][t][n'], n' = j*16+p
__device__ float g_w2b[2 * NP * 200];
__device__ float g_b2 [2 * NP];
__device__ float g_b3 [2 * NP];
__device__ float g_gates[800];
// mma B fragments, bf16 hi/lo packed per lane: uint4 = {hi_b0, hi_b1, lo_b0, lo_b1}
__device__ uint4 g_w3f[2 * 50 * 3328];        // [hd][nc50][ks13][nt8][lane32]  (fc3 w)
__device__ uint4 g_w2f[2u * 50 * 26 * 256];   // [hd][nb50][ks26][nt8][lane32]  (fc2a w, ks25=0)
// mma A fragments for U: per (tb,ks): [0..255]=hi plane [mt8][lane32], [256..511]=lo plane
__device__ uint4 g_Uf[128u * 26 * 512];       // ks25 = zeros

struct DecState {
    float h[HH];
    float c[HH];
    float r[2][HH];
    float v[2][NP];
    unsigned long long amax[2];
    int start, end, done;
};
__device__ DecState g_st;

// ---------------- helpers ----------------
__device__ __forceinline__ void split_pack(float x0, float x1, uint32_t& hi, uint32_t& lo) {
    __nv_bfloat16 h0 = __float2bfloat16(x0), h1 = __float2bfloat16(x1);
    hi = ((uint32_t)__bfloat16_as_ushort(h1) << 16) | __bfloat16_as_ushort(h0);
    __nv_bfloat16 l0 = __float2bfloat16(x0 - __bfloat162float(h0));
    __nv_bfloat16 l1 = __float2bfloat16(x1 - __bfloat162float(h1));
    lo = ((uint32_t)__bfloat16_as_ushort(l1) << 16) | __bfloat16_as_ushort(l0);
}
__device__ __forceinline__ void mma_bf(float* c, uint4 a, uint32_t b0, uint32_t b1) {
    asm("mma.sync.aligned.m16n8k16.row.col.f32.bf16.bf16.f32 "
        "{%0,%1,%2,%3}, {%4,%5,%6,%7}, {%8,%9}, {%0,%1,%2,%3};\n"
        : "+f"(c[0]), "+f"(c[1]), "+f"(c[2]), "+f"(c[3])
        : "r"(a.x), "r"(a.y), "r"(a.z), "r"(a.w), "r"(b0), "r"(b1));
}
// pool-16 maxout of G row segment + v segment
__device__ __forceinline__ float maxout16(const float* gp, const float* vp) {
    float m = -3.4e38f;
#pragma unroll
    for (int q = 0; q < 4; q++) {
        float4 gg = *(const float4*)(gp + q * 4);
        float4 vv = *(const float4*)(vp + q * 4);
        m = fmaxf(m, fmaxf(fmaxf(gg.x + vv.x, gg.y + vv.y), fmaxf(gg.z + vv.z, gg.w + vv.w)));
    }
    return m;
}
__device__ __forceinline__ float bf_lo(uint32_t u) {
    return __bfloat162float(__ushort_as_bfloat16((unsigned short)(u & 0xFFFF)));
}
__device__ __forceinline__ float bf_hi(uint32_t u) {
    return __bfloat162float(__ushort_as_bfloat16((unsigned short)(u >> 16)));
}

// ---------------- init ----------------
__global__ void k_init() {
    int tid = threadIdx.x;
    for (int j = tid; j < HH; j += blockDim.x) { g_st.h[j] = 0.f; g_st.c[j] = 0.f; }
    if (tid == 0) { g_st.start = 0; g_st.end = 0; g_st.done = 0; }
}

// ---------------- weight reorder + fragment prep ----------
__global__ void k_prep(const float* __restrict__ s2w, const float* __restrict__ s2b,
                       const float* __restrict__ s3w, const float* __restrict__ s3b,
                       const float* __restrict__ e2w, const float* __restrict__ e2b,
                       const float* __restrict__ e3w, const float* __restrict__ e3b) {
    int row = blockIdx.x;                 // 0..6399 = hd*NP + n'
    int hd  = row / NP;
    int np  = row - hd * NP;
    int j = np >> 4, p = np & 15;
    int src = p * HH + j;
    const float* w2 = hd ? e2w : s2w;
    const float* b2 = hd ? e2b : s2b;
    const float* w3 = hd ? e3w : s3w;
    const float* b3 = hd ? e3b : s3b;
    const float* w2row = w2 + (size_t)src * 600;
    const float* w3row = w3 + (size_t)src * 200;
    int tid = threadIdx.x;

    for (int k = tid; k < 200; k += 128) g_w2b[(size_t)row * 200 + k] = w2row[400 + k];

    {   // fc3 B fragments
        int nc = np >> 6, nl = np & 63, nt = nl >> 3, g = nl & 7;
        uint4* base = g_w3f + (size_t)(hd * 50 + nc) * 3328;
        for (int i = tid; i < 52; i += 128) {
            int ks = i >> 2, tk = i & 3;
            int k0 = ks * 16 + 2 * tk;
            float v0 = w3row[k0], v1 = w3row[k0 + 1];
            float v2 = (k0 + 8 < 200) ? w3row[k0 + 8] : 0.f;
            float v3 = (k0 + 9 < 200) ? w3row[k0 + 9] : 0.f;
            uint4 f;
            split_pack(v0, v1, f.x, f.z);
            split_pack(v2, v3, f.y, f.w);
            base[(ks * 8 + nt) * 32 + 4 * g + tk] = f;
        }
    }
    {   // fc2a B fragments (26 k-steps; ks 25 zero-padded)
        int nb = np >> 6, nl = np & 63, nt = nl >> 3, g = nl & 7;
        uint4* base = g_w2f + (size_t)(hd * 50 + nb) * 26 * 256;
        for (int i = tid; i < 104; i += 128) {
            int ks = i >> 2, tk = i & 3;
            uint4 f;
            if (ks < 25) {
                int k0 = ks * 16 + 2 * tk;
                split_pack(w2row[k0], w2row[k0 + 1], f.x, f.z);
                split_pack(w2row[k0 + 8], w2row[k0 + 9], f.y, f.w);
            } else {
                f.x = f.y = f.z = f.w = 0u;
            }
            base[ks * 256 + nt * 32 + 4 * g + tk] = f;
        }
    }
    if (tid == 0) { g_b2[row] = b2[src]; g_b3[row] = b3[src]; }
}

// ---------------- U -> A fragments (hi/lo planes; ks 25 zero-padded) ------------
__global__ void __launch_bounds__(256) k_splitU(const float* __restrict__ U) {
    int tb = blockIdx.x;
    int tid = threadIdx.x;
    int mt = tid >> 5, lane = tid & 31, g = lane >> 2, tk = lane & 3;
    const float* r0 = U + (size_t)(tb * 128 + mt * 16 + g) * 400;
    const float* r1 = r0 + 8 * 400;
    uint4* dst = g_Uf + (size_t)tb * 26 * 512;
    int fi = mt * 32 + lane;
    for (int ks = 0; ks < 25; ks++) {
        int k0 = ks * 16 + 2 * tk;
        uint4 hi, lo;
        split_pack(r0[k0], r0[k0 + 1], hi.x, lo.x);
        split_pack(r1[k0], r1[k0 + 1], hi.y, lo.y);
        split_pack(r0[k0 + 8], r0[k0 + 9], hi.z, lo.z);
        split_pack(r1[k0 + 8], r1[k0 + 9], hi.w, lo.w);
        dst[ks * 512 + fi] = hi;
        dst[ks * 512 + 256 + fi] = lo;
    }
    {   // pad ks 25 with zeros
        uint4 z; z.x = z.y = z.z = z.w = 0u;
        dst[25 * 512 + fi] = z;
        dst[25 * 512 + 256 + fi] = z;
    }
}

// ---------------- G = U @ w2a^T via mma (128x64 tile, 32-wide k slabs) ----------
__global__ void __launch_bounds__(256, 2) k_gemm_G_mma() {
    __shared__ uint4 As[1024];   // 2 ks: [ks0: hi 0..255 | lo 256..511][ks1: 512..1023]
    __shared__ uint4 Bs[512];    // 2 ks: [ks0: 0..255][ks1: 256..511]
    int nb = blockIdx.x, tb = blockIdx.y, hd = blockIdx.z;
    int tid = threadIdx.x, w = tid >> 5, lane = tid & 31;
    int wm = w & 3, wn = w >> 2;
    int g = lane >> 2, tk = lane & 3;
    float c[2][4][4];
#pragma unroll
    for (int a = 0; a < 2; a++)
#pragma unroll
        for (int b = 0; b < 4; b++)
#pragma unroll
            for (int q = 0; q < 4; q++) c[a][b][q] = 0.f;

    const uint4* Asrc = g_Uf + (size_t)tb * 26 * 512;
    const uint4* Bsrc = g_w2f + (size_t)(hd * 50 + nb) * 26 * 256;

    uint4 rA[4], rB[2];
#pragma unroll
    for (int i = 0; i < 4; i++) rA[i] = Asrc[tid + i * 256];
#pragma unroll
    for (int i = 0; i < 2; i++) rB[i] = Bsrc[tid + i * 256];

    for (int st = 0; st < 13; st++) {
        __syncthreads();
#pragma unroll
        for (int i = 0; i < 4; i++) As[tid + i * 256] = rA[i];
#pragma unroll
        for (int i = 0; i < 2; i++) Bs[tid + i * 256] = rB[i];
        __syncthreads();
        if (st + 1 < 13) {
#pragma unroll
            for (int i = 0; i < 4; i++) rA[i] = Asrc[(st + 1) * 1024 + tid + i * 256];
#pragma unroll
            for (int i = 0; i < 2; i++) rB[i] = Bsrc[(st + 1) * 512 + tid + i * 256];
        }
#pragma unroll
        for (int sub = 0; sub < 2; sub++) {
            uint4 Ah[2], Al[2], Bv[4];
#pragma unroll
            for (int m = 0; m < 2; m++) {
                int mt = wm * 2 + m;
                Ah[m] = As[sub * 512 + mt * 32 + lane];
                Al[m] = As[sub * 512 + 256 + mt * 32 + lane];
            }
#pragma unroll
            for (int n = 0; n < 4; n++) Bv[n] = Bs[sub * 256 + (wn * 4 + n) * 32 + lane];
#pragma unroll
            for (int m = 0; m < 2; m++)
#pragma unroll
                for (int n = 0; n < 4; n++) {
                    mma_bf(c[m][n], Ah[m], Bv[n].x, Bv[n].y);
                    mma_bf(c[m][n], Ah[m], Bv[n].z, Bv[n].w);
                    mma_bf(c[m][n], Al[m], Bv[n].x, Bv[n].y);
                }
        }
    }
#pragma unroll
    for (int m = 0; m < 2; m++) {
#pragma unroll
        for (int h = 0; h < 2; h++) {
            int rrow = tb * 128 + wm * 32 + m * 16 + g + h * 8;
            float* dst = g_G + ((size_t)hd * T_LEN + rrow) * NP + nb * 64 + wn * 32 + tk * 2;
#pragma unroll
            for (int n = 0; n < 4; n++) {
                float2 v;
                v.x = c[m][n][h * 2 + 0];
                v.y = c[m][n][h * 2 + 1];
                *(float2*)(dst + n * 8) = v;
            }
        }
    }
}

// ---------------- LSTM gates ----------------
__global__ void __launch_bounds__(256) k_gates(const float* __restrict__ U,
        const float* __restrict__ Wih, const float* __restrict__ Whh,
        const float* __restrict__ bih, const float* __restrict__ bhh) {
    if (g_st.done) return;
    int g = blockIdx.x * 8 + (threadIdx.x >> 5);
    int lane = threadIdx.x & 31;
    const float* Us = U + (size_t)g_st.start * 400;
    const float* Ue = U + (size_t)g_st.end * 400;
    const float* wr = Wih + (size_t)g * 800;
    const float* wh = Whh + (size_t)g * HH;
    float acc = 0.f;
#pragma unroll
    for (int q = 0; q < 3; q++) {
        int k = lane * 4 + q * 128;
        float4 w0 = *(const float4*)(wr + k);
        float4 w1 = *(const float4*)(wr + 400 + k);
        float4 x0 = *(const float4*)(Us + k);
        float4 x1 = *(const float4*)(Ue + k);
        acc += w0.x * x0.x + w0.y * x0.y + w0.z * x0.z + w0.w * x0.w;
        acc += w1.x * x1.x + w1.y * x1.y + w1.z * x1.z + w1.w * x1.w;
    }
    {
        int k = 384 + lane * 4;
        if (k < 400) {
            float4 w0 = *(const float4*)(wr + k);
            float4 w1 = *(const float4*)(wr + 400 + k);
            float4 x0 = *(const float4*)(Us + k);
            float4 x1 = *(const float4*)(Ue + k);
            acc += w0.x * x0.x + w0.y * x0.y + w0.z * x0.z + w0.w * x0.w;
            acc += w1.x * x1.x + w1.y * x1.y + w1.z * x1.z + w1.w * x1.w;
        }
    }
    for (int k = lane; k < HH; k += 32) acc += wh[k] * g_st.h[k];
    for (int o = 16; o; o >>= 1) acc += __shfl_xor_sync(0xffffffffu, acc, o);
    if (lane == 0) g_gates[g] = acc + bih[g] + bhh[g];
}

// ---------------- activation + state update ----------------
__global__ void k_act() {
    if (threadIdx.x == 0) { g_st.amax[0] = 0ull; g_st.amax[1] = 0ull; }
    if (g_st.done) return;
    int j = threadIdx.x;
    if (j < HH) {
        float ig = 1.f / (1.f + expf(-g_gates[j]));
        float fg = 1.f / (1.f + expf(-g_gates[200 + j]));
        float gg = tanhf(g_gates[400 + j]);
        float og = 1.f / (1.f + expf(-g_gates[600 + j]));
        float cn = fg * g_st.c[j] + ig * gg;
        g_st.c[j] = cn;
        g_st.h[j] = og * tanhf(cn);
    }
}

// ---------------- r = tanh(fc1w @ [h, U[start], U[end]]) ----------------
__global__ void __launch_bounds__(256) k_r(const float* __restrict__ U,
        const float* __restrict__ s1w, const float* __restrict__ e1w) {
    if (g_st.done) return;
    int idx = blockIdx.x * 8 + (threadIdx.x >> 5);
    int lane = threadIdx.x & 31;
    int hd = idx / HH, j = idx - hd * HH;
    const float* w = (hd ? e1w : s1w) + (size_t)j * 1000;
    const float* Us = U + (size_t)g_st.start * 400;
    const float* Ue = U + (size_t)g_st.end * 400;
    float acc = 0.f;
    for (int k = lane; k < HH; k += 32) acc += w[k] * g_st.h[k];
#pragma unroll
    for (int q = 0; q < 3; q++) {
        int k = lane * 4 + q * 128;
        float4 w0 = *(const float4*)(w + 200 + k);
        float4 w1 = *(const float4*)(w + 600 + k);
        float4 x0 = *(const float4*)(Us + k);
        float4 x1 = *(const float4*)(Ue + k);
        acc += w0.x * x0.x + w0.y * x0.y + w0.z * x0.z + w0.w * x0.w;
        acc += w1.x * x1.x + w1.y * x1.y + w1.z * x1.z + w1.w * x1.w;
    }
    {
        int k = 384 + lane * 4;
        if (k < 400) {
            float4 w0 = *(const float4*)(w + 200 + k);
            float4 w1 = *(const float4*)(w + 600 + k);
            float4 x0 = *(const float4*)(Us + k);
            float4 x1 = *(const float4*)(Ue + k);
            acc += w0.x * x0.x + w0.y * x0.y + w0.z * x0.z + w0.w * x0.w;
            acc += w1.x * x1.x + w1.y * x1.y + w1.z * x1.z + w1.w * x1.w;
        }
    }
    for (int o = 16; o; o >>= 1) acc += __shfl_xor_sync(0xffffffffu, acc, o);
    if (lane == 0) g_st.r[hd][j] = tanhf(acc);
}

// ---------------- v = w2b @ r + b2 ----------------
__global__ void k_v() {
    if (g_st.done) return;
    int gw = (blockIdx.x * blockDim.x + threadIdx.x) >> 5;
    int lane = threadIdx.x & 31;
    if (gw >= 2 * NP) return;
    int hd = gw / NP, n = gw - hd * NP;
    const float* w = g_w2b + ((size_t)hd * NP + n) * 200;
    const float* r = g_st.r[hd];
    float acc = 0.f;
    for (int k = lane; k < 200; k += 32) acc += w[k] * r[k];
    for (int o = 16; o; o >>= 1) acc += __shfl_xor_sync(0xffffffffu, acc, o);
    if (lane == 0) g_st.v[hd][n] = acc + g_b2[hd * NP + n];
}

// ---------------- score: fused maxout(G+v) + fc3 mma + maxout + fc4 + argmax ----
// smem bytes:
#define SC_AFH 0
#define SC_AFL 53248
#define SC_BC  106496
#define SC_W4  159744
#define SC_B3  185344
#define SC_VS  198144
#define SC_B4  210944
#define SC_M2  211008
#define SC_SMEM 213056

__global__ void __launch_bounds__(512, 1) k_score_mma(
        const float* __restrict__ s4w, const float* __restrict__ s4b,
        const float* __restrict__ e4w, const float* __restrict__ e4b,
        float* __restrict__ out, int iter) {
    extern __shared__ char smc[];
    int hd = blockIdx.y;
    int t0 = blockIdx.x * 128;
    float* outh = out + (size_t)hd * 4 * T_LEN + (size_t)iter * T_LEN;

    if (g_st.done) {   // frozen: alpha[iter] = alpha[iter-1] (only possible iter>=2)
        for (int t = threadIdx.x; t < 128; t += 512)
            outh[t0 + t] = outh[t0 + t - T_LEN];
        return;
    }

    uint4* AFH = (uint4*)(smc + SC_AFH);
    uint4* AFL = (uint4*)(smc + SC_AFL);
    uint4* BC  = (uint4*)(smc + SC_BC);
    float* w4T = (float*)(smc + SC_W4);
    float* b3s = (float*)(smc + SC_B3);
    float* vs  = (float*)(smc + SC_VS);
    float* b4s = (float*)(smc + SC_B4);
    float* m2c = (float*)(smc + SC_M2);

    int tid = threadIdx.x, w = tid >> 5, lane = tid & 31;
    int g = lane >> 2, tk = lane & 3;

    const float* w4 = hd ? e4w : s4w;
    for (int i = tid; i < 6400; i += 512) {
        int k = i >> 4, p = i & 15;
        w4T[i] = w4[(size_t)p * 400 + k];
    }
    for (int i = tid; i < NP; i += 512) {
        b3s[i] = g_b3[hd * NP + i];
        vs[i]  = g_st.v[hd][i];
    }
    if (tid < 16) b4s[tid] = (hd ? e4b : s4b)[tid];
    __syncthreads();

    // ---- A-build: fused pool-16 maxout of (G + v), split to bf16 hi/lo fragments
    {
        int mt = w & 7;
        int ksb = (w >> 3) ? 7 : 0;
        int kse = (w >> 3) ? 13 : 7;
        const float* gr0 = g_G + ((size_t)hd * T_LEN + t0 + mt * 16 + g) * NP;
        const float* gr1 = gr0 + (size_t)8 * NP;
        int fi = mt * 32 + lane;
        for (int ks = ksb; ks < kse; ks++) {
            int k0 = ks * 16 + 2 * tk;
            uint4 hi, lo;
            float a0 = maxout16(gr0 + (size_t)k0 * 16, vs + k0 * 16);
            float a1 = maxout16(gr0 + (size_t)(k0 + 1) * 16, vs + (k0 + 1) * 16);
            float b0 = maxout16(gr1 + (size_t)k0 * 16, vs + k0 * 16);
            float b1 = maxout16(gr1 + (size_t)(k0 + 1) * 16, vs + (k0 + 1) * 16);
            split_pack(a0, a1, hi.x, lo.x);
            split_pack(b0, b1, hi.y, lo.y);
            if (k0 + 8 < 200) {
                float a2 = maxout16(gr0 + (size_t)(k0 + 8) * 16, vs + (k0 + 8) * 16);
                float a3 = maxout16(gr0 + (size_t)(k0 + 9) * 16, vs + (k0 + 9) * 16);
                float b2 = maxout16(gr1 + (size_t)(k0 + 8) * 16, vs + (k0 + 8) * 16);
                float b3v = maxout16(gr1 + (size_t)(k0 + 9) * 16, vs + (k0 + 9) * 16);
                split_pack(a2, a3, hi.z, lo.z);
                split_pack(b2, b3v, hi.w, lo.w);
            } else { hi.z = hi.w = lo.z = lo.w = 0u; }
            AFH[ks * 256 + fi] = hi;
            AFL[ks * 256 + fi] = lo;
        }
    }
    __syncthreads();

    // ---- fc4 m1-part: reconstruct m1 = hi + lo from fragments ----
    int row4 = tid >> 2, q4 = tid & 3;       // 4 threads per row, 4 p's each
    float p4[4];
#pragma unroll
    for (int i = 0; i < 4; i++) p4[i] = 0.f;
    {
        int mt = row4 >> 4, rem = row4 & 15, h = rem >> 3, gr = rem & 7;
        for (int ks = 0; ks < 13; ks++) {
#pragma unroll
            for (int tkk = 0; tkk < 4; tkk++) {
                int idx = ks * 256 + mt * 32 + gr * 4 + tkk;
                uint4 H = AFH[idx], L = AFL[idx];
                uint32_t ua = h ? H.y : H.x, la = h ? L.y : L.x;
                uint32_t ub = h ? H.w : H.z, lb = h ? L.w : L.z;
                int k0 = ks * 16 + 2 * tkk;
                float m0 = bf_lo(ua) + bf_lo(la);
                float m1v = bf_hi(ua) + bf_hi(la);
                const float* wp0 = w4T + k0 * 16 + q4 * 4;
#pragma unroll
                for (int pp = 0; pp < 4; pp++)
                    p4[pp] += m0 * wp0[pp] + m1v * wp0[16 + pp];
                if (k0 + 8 < 200) {
                    float m2 = bf_lo(ub) + bf_lo(lb);
                    float m3 = bf_hi(ub) + bf_hi(lb);
                    const float* wp8 = w4T + (k0 + 8) * 16 + q4 * 4;
#pragma unroll
                    for (int pp = 0; pp < 4; pp++)
                        p4[pp] += m2 * wp8[pp] + m3 * wp8[16 + pp];
                }
            }
        }
    }

    int wm = w & 7, wn = w >> 3;   // warp tile: rows 16*wm, cols 32*wn
    const uint4* Bsrc = g_w3f + (size_t)hd * 50 * 3328;

    // preload chunk 0 B into registers
    uint4 rb[7];
#pragma unroll
    for (int i = 0; i < 7; i++) {
        int idx = tid + i * 512;
        if (idx < 3328) rb[i] = Bsrc[idx];
    }

    for (int nc = 0; nc < 50; nc++) {
        // store staged B chunk to smem
#pragma unroll
        for (int i = 0; i < 7; i++) {
            int idx = tid + i * 512;
            if (idx < 3328) BC[idx] = rb[i];
        }
        __syncthreads();
        // prefetch next chunk's B while computing this one
        if (nc + 1 < 50) {
#pragma unroll
            for (int i = 0; i < 7; i++) {
                int idx = tid + i * 512;
                if (idx < 3328) rb[i] = Bsrc[(size_t)(nc + 1) * 3328 + idx];
            }
        }

        float c[4][4];
#pragma unroll
        for (int b = 0; b < 4; b++)
#pragma unroll
            for (int qq = 0; qq < 4; qq++) c[b][qq] = 0.f;

        for (int ks = 0; ks < 13; ks++) {
            uint4 Ah = AFH[ks * 256 + wm * 32 + lane];
            uint4 Al = AFL[ks * 256 + wm * 32 + lane];
            uint4 Bv[4];
#pragma unroll
            for (int n = 0; n < 4; n++) Bv[n] = BC[(ks * 8 + wn * 4 + n) * 32 + lane];
#pragma unroll
            for (int n = 0; n < 4; n++) {
                mma_bf(c[n], Ah, Bv[n].x, Bv[n].y);
                mma_bf(c[n], Ah, Bv[n].z, Bv[n].w);
                mma_bf(c[n], Al, Bv[n].x, Bv[n].y);
            }
        }

        // maxout (pool 16) -> m2c[128][4]
        {
            int rloc = wm * 16 + g;
#pragma unroll
            for (int grp = 0; grp < 2; grp++) {
                int n0 = grp * 2;
                int colb = nc * 64 + wn * 32 + grp * 16 + tk * 2;
                float b3a0 = b3s[colb],     b3a1 = b3s[colb + 1];
                float b3b0 = b3s[colb + 8], b3b1 = b3s[colb + 9];
                float vlo = fmaxf(fmaxf(c[n0][0] + b3a0, c[n0][1] + b3a1),
                                  fmaxf(c[n0 + 1][0] + b3b0, c[n0 + 1][1] + b3b1));
                float vhi = fmaxf(fmaxf(c[n0][2] + b3a0, c[n0][3] + b3a1),
                                  fmaxf(c[n0 + 1][2] + b3b0, c[n0 + 1][3] + b3b1));
                vlo = fmaxf(vlo, __shfl_xor_sync(0xffffffffu, vlo, 1));
                vlo = fmaxf(vlo, __shfl_xor_sync(0xffffffffu, vlo, 2));
                vhi = fmaxf(vhi, __shfl_xor_sync(0xffffffffu, vhi, 1));
                vhi = fmaxf(vhi, __shfl_xor_sync(0xffffffffu, vhi, 2));
                if (tk == 0) {
                    m2c[rloc * 4 + wn * 2 + grp] = vlo;
                    m2c[(rloc + 8) * 4 + wn * 2 + grp] = vhi;
                }
            }
        }
        __syncthreads();

        // fc4 partial from this chunk's 4 pooled values
        // (no trailing sync needed: BC reads all precede the sync above; the next
        //  iteration's top-of-loop sync orders m2c rewrites after these reads)
        {
            float mv0 = m2c[row4 * 4 + 0], mv1 = m2c[row4 * 4 + 1];
            float mv2 = m2c[row4 * 4 + 2], mv3 = m2c[row4 * 4 + 3];
            const float* w0 = w4T + (200 + nc * 4) * 16 + q4 * 4;
#pragma unroll
            for (int pp = 0; pp < 4; pp++)
                p4[pp] += mv0 * w0[pp] + mv1 * w0[16 + pp] +
                          mv2 * w0[32 + pp] + mv3 * w0[48 + pp];
        }
    }

    // ---- final: pool-max over fc4, write alpha, warp-reduced packed argmax ----
    {
        float v = p4[0] + b4s[q4 * 4];
#pragma unroll
        for (int pp = 1; pp < 4; pp++) v = fmaxf(v, p4[pp] + b4s[q4 * 4 + pp]);
        v = fmaxf(v, __shfl_xor_sync(0xffffffffu, v, 1));
        v = fmaxf(v, __shfl_xor_sync(0xffffffffu, v, 2));
        if (q4 == 0) outh[t0 + row4] = v;
        int trow = t0 + row4;
        unsigned key = __float_as_uint(v);
        key = (key & 0x80000000u) ? ~key : (key | 0x80000000u);
        unsigned long long pk =
            ((unsigned long long)key << 32) | (unsigned long long)(0xFFFFFFFFu - (unsigned)trow);
#pragma unroll
        for (int o = 16; o; o >>= 1) {
            unsigned long long other = __shfl_xor_sync(0xffffffffu, pk, o);
            if (other > pk) pk = other;
        }
        if (lane == 0) atomicMax(&g_st.amax[hd], pk);
    }
}

// ---------------- argmax decode + done/start/end update ----------------
__global__ void k_update(int iter) {
    if (g_st.done) return;
    unsigned long long a0 = g_st.amax[0], a1 = g_st.amax[1];
    int ns = (int)(0xFFFFFFFFu - (unsigned)(a0 & 0xFFFFFFFFull));
    int ne = (int)(0xFFFFFFFFu - (unsigned)(a1 & 0xFFFFFFFFull));
    if (iter > 0 && ns == g_st.start && ne == g_st.end) g_st.done = 1;
    g_st.start = ns;
    g_st.end = ne;
}

// ---------------- launch ----------------
extern "C" void kernel_launch(void* const* d_in, const int* in_sizes, int n_in,
                              void* d_out, int out_size) {
    const float* U    = (const float*)d_in[0];
    const float* Wih  = (const float*)d_in[1];
    const float* Whh  = (const float*)d_in[2];
    const float* bih  = (const float*)d_in[3];
    const float* bhh  = (const float*)d_in[4];
    const float* s1w  = (const float*)d_in[5];
    const float* s2w  = (const float*)d_in[6];
    const float* s2b  = (const float*)d_in[7];
    const float* s3w  = (const float*)d_in[8];
    const float* s3b  = (const float*)d_in[9];
    const float* s4w  = (const float*)d_in[10];
    const float* s4b  = (const float*)d_in[11];
    const float* e1w  = (const float*)d_in[12];
    const float* e2w  = (const float*)d_in[13];
    const float* e2b  = (const float*)d_in[14];
    const float* e3w  = (const float*)d_in[15];
    const float* e3b  = (const float*)d_in[16];
    const float* e4w  = (const float*)d_in[17];
    const float* e4b  = (const float*)d_in[18];
    float* out = (float*)d_out;

    cudaFuncSetAttribute(k_score_mma, cudaFuncAttributeMaxDynamicSharedMemorySize, SC_SMEM);

    k_init<<<1, 256>>>();
    k_prep<<<6400, 128>>>(s2w, s2b, s3w, s3b, e2w, e2b, e3w, e3b);
    k_splitU<<<128, 256>>>(U);

    dim3 gG(50, 128, 2);
    k_gemm_G_mma<<<gG, 256>>>();

    for (int it = 0; it < 4; ++it) {
        k_gates<<<100, 256>>>(U, Wih, Whh, bih, bhh);
        k_act<<<1, 256>>>();
        k_r<<<50, 256>>>(U, s1w, e1w);
        k_v<<<800, 256>>>();
        dim3 gs(T_LEN / 128, 2);
        k_score_mma<<<gs, 512, SC_SMEM>>>(s4w, s4b, e4w, e4b, out, it);
        if (it < 3) k_update<<<1, 1>>>(it);
    }
}

// round 14
// speedup vs baseline: 3.4223x; 1.1260x over previous
#include <cuda_runtime.h>
#include <cuda_bf16.h>
#include <math.h>
#include <stdint.h>

// ---------------- problem constants ----------------
#define T_LEN 16384
#define HH    200
#define NP    3200      // POOL*H

// ---------------- device scratch (static; no allocations allowed) ----------------
__device__ float g_G[2u * T_LEN * NP];        // [hd][t][n'], n' = j*16+p
__device__ float g_w2b[2 * NP * 200];
__device__ float g_b2 [2 * NP];
__device__ float g_b3 [2 * NP];
__device__ float g_gates[800];
// mma B fragments, bf16 hi/lo packed per lane: uint4 = {hi_b0, hi_b1, lo_b0, lo_b1}
__device__ uint4 g_w3f[2 * 50 * 3328];        // [hd][nc50][ks13][nt8][lane32]  (fc3 w)
__device__ uint4 g_w2f[2u * 50 * 26 * 256];   // [hd][nb50][ks26][nt8][lane32]  (fc2a w, ks25=0)
// mma A fragments for U: per (tb,ks): [0..255]=hi plane [mt8][lane32], [256..511]=lo plane
__device__ uint4 g_Uf[128u * 26 * 512];       // ks25 = zeros

struct DecState {
    float h[HH];
    float c[HH];
    float r[2][HH];
    float v[2][NP];
    unsigned long long amax[2];
    int start, end, done;
};
__device__ DecState g_st;

// ---------------- helpers ----------------
__device__ __forceinline__ uint32_t smem_u32(const void* p) {
    uint32_t a;
    asm("{ .reg .u64 t; cvta.to.shared.u64 t, %1; cvt.u32.u64 %0, t; }" : "=r"(a) : "l"(p));
    return a;
}
__device__ __forceinline__ void cp16(void* sp, const void* gp) {
    asm volatile("cp.async.cg.shared.global [%0], [%1], 16;\n"
                 :: "r"(smem_u32(sp)), "l"(gp));
}
#define CP_COMMIT() asm volatile("cp.async.commit_group;\n" ::: "memory")
#define CP_WAIT(N)  asm volatile("cp.async.wait_group %0;\n" :: "n"(N) : "memory")

__device__ __forceinline__ void split_pack(float x0, float x1, uint32_t& hi, uint32_t& lo) {
    __nv_bfloat16 h0 = __float2bfloat16(x0), h1 = __float2bfloat16(x1);
    hi = ((uint32_t)__bfloat16_as_ushort(h1) << 16) | __bfloat16_as_ushort(h0);
    __nv_bfloat16 l0 = __float2bfloat16(x0 - __bfloat162float(h0));
    __nv_bfloat16 l1 = __float2bfloat16(x1 - __bfloat162float(h1));
    lo = ((uint32_t)__bfloat16_as_ushort(l1) << 16) | __bfloat16_as_ushort(l0);
}
__device__ __forceinline__ void mma_bf(float* c, uint4 a, uint32_t b0, uint32_t b1) {
    asm("mma.sync.aligned.m16n8k16.row.col.f32.bf16.bf16.f32 "
        "{%0,%1,%2,%3}, {%4,%5,%6,%7}, {%8,%9}, {%0,%1,%2,%3};\n"
        : "+f"(c[0]), "+f"(c[1]), "+f"(c[2]), "+f"(c[3])
        : "r"(a.x), "r"(a.y), "r"(a.z), "r"(a.w), "r"(b0), "r"(b1));
}
__device__ __forceinline__ float maxout16(const float* gp, const float* vp) {
    float m = -3.4e38f;
#pragma unroll
    for (int q = 0; q < 4; q++) {
        float4 gg = *(const float4*)(gp + q * 4);
        float4 vv = *(const float4*)(vp + q * 4);
        m = fmaxf(m, fmaxf(fmaxf(gg.x + vv.x, gg.y + vv.y), fmaxf(gg.z + vv.z, gg.w + vv.w)));
    }
    return m;
}
__device__ __forceinline__ float bf_lo(uint32_t u) {
    return __bfloat162float(__ushort_as_bfloat16((unsigned short)(u & 0xFFFF)));
}
__device__ __forceinline__ float bf_hi(uint32_t u) {
    return __bfloat162float(__ushort_as_bfloat16((unsigned short)(u >> 16)));
}

// ---------------- init ----------------
__global__ void k_init() {
    int tid = threadIdx.x;
    for (int j = tid; j < HH; j += blockDim.x) { g_st.h[j] = 0.f; g_st.c[j] = 0.f; }
    if (tid == 0) { g_st.start = 0; g_st.end = 0; g_st.done = 0; }
}

// ---------------- weight reorder + fragment prep ----------
__global__ void k_prep(const float* __restrict__ s2w, const float* __restrict__ s2b,
                       const float* __restrict__ s3w, const float* __restrict__ s3b,
                       const float* __restrict__ e2w, const float* __restrict__ e2b,
                       const float* __restrict__ e3w, const float* __restrict__ e3b) {
    int row = blockIdx.x;                 // 0..6399 = hd*NP + n'
    int hd  = row / NP;
    int np  = row - hd * NP;
    int j = np >> 4, p = np & 15;
    int src = p * HH + j;
    const float* w2 = hd ? e2w : s2w;
    const float* b2 = hd ? e2b : s2b;
    const float* w3 = hd ? e3w : s3w;
    const float* b3 = hd ? e3b : s3b;
    const float* w2row = w2 + (size_t)src * 600;
    const float* w3row = w3 + (size_t)src * 200;
    int tid = threadIdx.x;

    for (int k = tid; k < 200; k += 128) g_w2b[(size_t)row * 200 + k] = w2row[400 + k];

    {   // fc3 B fragments
        int nc = np >> 6, nl = np & 63, nt = nl >> 3, g = nl & 7;
        uint4* base = g_w3f + (size_t)(hd * 50 + nc) * 3328;
        for (int i = tid; i < 52; i += 128) {
            int ks = i >> 2, tk = i & 3;
            int k0 = ks * 16 + 2 * tk;
            float v0 = w3row[k0], v1 = w3row[k0 + 1];
            float v2 = (k0 + 8 < 200) ? w3row[k0 + 8] : 0.f;
            float v3 = (k0 + 9 < 200) ? w3row[k0 + 9] : 0.f;
            uint4 f;
            split_pack(v0, v1, f.x, f.z);
            split_pack(v2, v3, f.y, f.w);
            base[(ks * 8 + nt) * 32 + 4 * g + tk] = f;
        }
    }
    {   // fc2a B fragments (26 k-steps; ks 25 zero-padded)
        int nb = np >> 6, nl = np & 63, nt = nl >> 3, g = nl & 7;
        uint4* base = g_w2f + (size_t)(hd * 50 + nb) * 26 * 256;
        for (int i = tid; i < 104; i += 128) {
            int ks = i >> 2, tk = i & 3;
            uint4 f;
            if (ks < 25) {
                int k0 = ks * 16 + 2 * tk;
                split_pack(w2row[k0], w2row[k0 + 1], f.x, f.z);
                split_pack(w2row[k0 + 8], w2row[k0 + 9], f.y, f.w);
            } else {
                f.x = f.y = f.z = f.w = 0u;
            }
            base[ks * 256 + nt * 32 + 4 * g + tk] = f;
        }
    }
    if (tid == 0) { g_b2[row] = b2[src]; g_b3[row] = b3[src]; }
}

// ---------------- U -> A fragments (hi/lo planes; ks 25 zero-padded) ------------
__global__ void __launch_bounds__(256) k_splitU(const float* __restrict__ U) {
    int tb = blockIdx.x;
    int tid = threadIdx.x;
    int mt = tid >> 5, lane = tid & 31, g = lane >> 2, tk = lane & 3;
    const float* r0 = U + (size_t)(tb * 128 + mt * 16 + g) * 400;
    const float* r1 = r0 + 8 * 400;
    uint4* dst = g_Uf + (size_t)tb * 26 * 512;
    int fi = mt * 32 + lane;
    for (int ks = 0; ks < 25; ks++) {
        int k0 = ks * 16 + 2 * tk;
        uint4 hi, lo;
        split_pack(r0[k0], r0[k0 + 1], hi.x, lo.x);
        split_pack(r1[k0], r1[k0 + 1], hi.y, lo.y);
        split_pack(r0[k0 + 8], r0[k0 + 9], hi.z, lo.z);
        split_pack(r1[k0 + 8], r1[k0 + 9], hi.w, lo.w);
        dst[ks * 512 + fi] = hi;
        dst[ks * 512 + 256 + fi] = lo;
    }
    {
        uint4 z; z.x = z.y = z.z = z.w = 0u;
        dst[25 * 512 + fi] = z;
        dst[25 * 512 + 256 + fi] = z;
    }
}

// ---------------- G = U @ w2a^T via mma (128x128 tile, cp.async pipeline) -------
__global__ void __launch_bounds__(256, 2) k_gemm_G_mma() {
    __shared__ uint4 stg[2][1024];   // [buf][A hi 0..255 | A lo 256..511 | B 512..1023]
    int nb2 = blockIdx.x;            // 0..24 (128-col chunks)
    int tb = blockIdx.y, hd = blockIdx.z;
    int tid = threadIdx.x, w = tid >> 5, lane = tid & 31;
    int wm = w & 1, wn = w >> 1;     // warp tile: rows 64*wm, cols 32*wn
    int g = lane >> 2, tk = lane & 3;

    float c[4][4][4];
#pragma unroll
    for (int m = 0; m < 4; m++)
#pragma unroll
        for (int n = 0; n < 4; n++)
#pragma unroll
            for (int q = 0; q < 4; q++) c[m][n][q] = 0.f;

    const uint4* Asrc = g_Uf + (size_t)tb * 26 * 512;
    const uint4* B0 = g_w2f + (size_t)(hd * 50 + nb2 * 2) * 26 * 256;
    const uint4* B1 = g_w2f + (size_t)(hd * 50 + nb2 * 2 + 1) * 26 * 256;

#define G_FILL(ks, buf)                                                     \
    {                                                                       \
        _Pragma("unroll")                                                   \
        for (int i_ = 0; i_ < 4; i_++) {                                    \
            int idx_ = tid + i_ * 256;                                      \
            const uint4* src_;                                              \
            if (idx_ < 512)      src_ = Asrc + (ks) * 512 + idx_;           \
            else if (idx_ < 768) src_ = B0 + (ks) * 256 + (idx_ - 512);     \
            else                 src_ = B1 + (ks) * 256 + (idx_ - 768);     \
            cp16(&stg[buf][idx_], src_);                                    \
        }                                                                   \
        CP_COMMIT();                                                        \
    }

    G_FILL(0, 0);
    G_FILL(1, 1);

    for (int ks = 0; ks < 26; ks++) {
        int buf = ks & 1;
        CP_WAIT(1);
        __syncthreads();
        uint4 Bv[4];
#pragma unroll
        for (int n = 0; n < 4; n++)
            Bv[n] = stg[buf][512 + (wn >> 1) * 256 + ((wn & 1) * 4 + n) * 32 + lane];
#pragma unroll
        for (int m = 0; m < 4; m++) {
            int mt = wm * 4 + m;
            uint4 Ah = stg[buf][mt * 32 + lane];
            uint4 Al = stg[buf][256 + mt * 32 + lane];
#pragma unroll
            for (int n = 0; n < 4; n++) {
                mma_bf(c[m][n], Ah, Bv[n].x, Bv[n].y);
                mma_bf(c[m][n], Ah, Bv[n].z, Bv[n].w);
                mma_bf(c[m][n], Al, Bv[n].x, Bv[n].y);
            }
        }
        __syncthreads();
        if (ks + 2 < 26) G_FILL(ks + 2, buf);
    }
#undef G_FILL

#pragma unroll
    for (int m = 0; m < 4; m++) {
#pragma unroll
        for (int h = 0; h < 2; h++) {
            int rrow = tb * 128 + wm * 64 + m * 16 + g + h * 8;
            float* dst = g_G + ((size_t)hd * T_LEN + rrow) * NP + nb2 * 128 + wn * 32 + tk * 2;
#pragma unroll
            for (int n = 0; n < 4; n++) {
                float2 v;
                v.x = c[m][n][h * 2 + 0];
                v.y = c[m][n][h * 2 + 1];
                *(float2*)(dst + n * 8) = v;
            }
        }
    }
}

// ---------------- LSTM gates ----------------
__global__ void __launch_bounds__(256) k_gates(const float* __restrict__ U,
        const float* __restrict__ Wih, const float* __restrict__ Whh,
        const float* __restrict__ bih, const float* __restrict__ bhh) {
    if (g_st.done) return;
    int g = blockIdx.x * 8 + (threadIdx.x >> 5);
    int lane = threadIdx.x & 31;
    const float* Us = U + (size_t)g_st.start * 400;
    const float* Ue = U + (size_t)g_st.end * 400;
    const float* wr = Wih + (size_t)g * 800;
    const float* wh = Whh + (size_t)g * HH;
    float acc = 0.f;
#pragma unroll
    for (int q = 0; q < 3; q++) {
        int k = lane * 4 + q * 128;
        float4 w0 = *(const float4*)(wr + k);
        float4 w1 = *(const float4*)(wr + 400 + k);
        float4 x0 = *(const float4*)(Us + k);
        float4 x1 = *(const float4*)(Ue + k);
        acc += w0.x * x0.x + w0.y * x0.y + w0.z * x0.z + w0.w * x0.w;
        acc += w1.x * x1.x + w1.y * x1.y + w1.z * x1.z + w1.w * x1.w;
    }
    {
        int k = 384 + lane * 4;
        if (k < 400) {
            float4 w0 = *(const float4*)(wr + k);
            float4 w1 = *(const float4*)(wr + 400 + k);
            float4 x0 = *(const float4*)(Us + k);
            float4 x1 = *(const float4*)(Ue + k);
            acc += w0.x * x0.x + w0.y * x0.y + w0.z * x0.z + w0.w * x0.w;
            acc += w1.x * x1.x + w1.y * x1.y + w1.z * x1.z + w1.w * x1.w;
        }
    }
    for (int k = lane; k < HH; k += 32) acc += wh[k] * g_st.h[k];
    for (int o = 16; o; o >>= 1) acc += __shfl_xor_sync(0xffffffffu, acc, o);
    if (lane == 0) g_gates[g] = acc + bih[g] + bhh[g];
}

// ---------------- activation + state update ----------------
__global__ void k_act() {
    if (threadIdx.x == 0) { g_st.amax[0] = 0ull; g_st.amax[1] = 0ull; }
    if (g_st.done) return;
    int j = threadIdx.x;
    if (j < HH) {
        float ig = 1.f / (1.f + expf(-g_gates[j]));
        float fg = 1.f / (1.f + expf(-g_gates[200 + j]));
        float gg = tanhf(g_gates[400 + j]);
        float og = 1.f / (1.f + expf(-g_gates[600 + j]));
        float cn = fg * g_st.c[j] + ig * gg;
        g_st.c[j] = cn;
        g_st.h[j] = og * tanhf(cn);
    }
}

// ---------------- r = tanh(fc1w @ [h, U[start], U[end]]) ----------------
__global__ void __launch_bounds__(256) k_r(const float* __restrict__ U,
        const float* __restrict__ s1w, const float* __restrict__ e1w) {
    if (g_st.done) return;
    int idx = blockIdx.x * 8 + (threadIdx.x >> 5);
    int lane = threadIdx.x & 31;
    int hd = idx / HH, j = idx - hd * HH;
    const float* w = (hd ? e1w : s1w) + (size_t)j * 1000;
    const float* Us = U + (size_t)g_st.start * 400;
    const float* Ue = U + (size_t)g_st.end * 400;
    float acc = 0.f;
    for (int k = lane; k < HH; k += 32) acc += w[k] * g_st.h[k];
#pragma unroll
    for (int q = 0; q < 3; q++) {
        int k = lane * 4 + q * 128;
        float4 w0 = *(const float4*)(w + 200 + k);
        float4 w1 = *(const float4*)(w + 600 + k);
        float4 x0 = *(const float4*)(Us + k);
        float4 x1 = *(const float4*)(Ue + k);
        acc += w0.x * x0.x + w0.y * x0.y + w0.z * x0.z + w0.w * x0.w;
        acc += w1.x * x1.x + w1.y * x1.y + w1.z * x1.z + w1.w * x1.w;
    }
    {
        int k = 384 + lane * 4;
        if (k < 400) {
            float4 w0 = *(const float4*)(w + 200 + k);
            float4 w1 = *(const float4*)(w + 600 + k);
            float4 x0 = *(const float4*)(Us + k);
            float4 x1 = *(const float4*)(Ue + k);
            acc += w0.x * x0.x + w0.y * x0.y + w0.z * x0.z + w0.w * x0.w;
            acc += w1.x * x1.x + w1.y * x1.y + w1.z * x1.z + w1.w * x1.w;
        }
    }
    for (int o = 16; o; o >>= 1) acc += __shfl_xor_sync(0xffffffffu, acc, o);
    if (lane == 0) g_st.r[hd][j] = tanhf(acc);
}

// ---------------- v = w2b @ r + b2 ----------------
__global__ void k_v() {
    if (g_st.done) return;
    int gw = (blockIdx.x * blockDim.x + threadIdx.x) >> 5;
    int lane = threadIdx.x & 31;
    if (gw >= 2 * NP) return;
    int hd = gw / NP, n = gw - hd * NP;
    const float* w = g_w2b + ((size_t)hd * NP + n) * 200;
    const float* r = g_st.r[hd];
    float acc = 0.f;
    for (int k = lane; k < 200; k += 32) acc += w[k] * r[k];
    for (int o = 16; o; o >>= 1) acc += __shfl_xor_sync(0xffffffffu, acc, o);
    if (lane == 0) g_st.v[hd][n] = acc + g_b2[hd * NP + n];
}

// ---------------- score: fused maxout(G+v) + fc3 mma + maxout + fc4 + argmax ----
// smem map (bytes):
#define SC_AFH 0
#define SC_AFL 53248
#define SC_BC  106496        // 104 KB (13 ks x 2 half x 256 uint4); vs overlays here
#define SC_B3  212992        // 12800
#define SC_M2  225792        // 128*8*4 = 4096
#define SC_W4C 229888        // 512
#define SC_B4  230400        // 64
#define SC_SMEM 230464

__global__ void __launch_bounds__(512, 1) k_score_mma(
        const float* __restrict__ s4w, const float* __restrict__ s4b,
        const float* __restrict__ e4w, const float* __restrict__ e4b,
        float* __restrict__ out, int iter) {
    extern __shared__ char smc[];
    int hd = blockIdx.y;
    int t0 = blockIdx.x * 128;
    float* outh = out + (size_t)hd * 4 * T_LEN + (size_t)iter * T_LEN;

    if (g_st.done) {   // frozen: alpha[iter] = alpha[iter-1] (only possible iter>=2)
        for (int t = threadIdx.x; t < 128; t += 512)
            outh[t0 + t] = outh[t0 + t - T_LEN];
        return;
    }

    uint4* AFH = (uint4*)(smc + SC_AFH);
    uint4* AFL = (uint4*)(smc + SC_AFL);
    uint4* BC  = (uint4*)(smc + SC_BC);
    float* b3s = (float*)(smc + SC_B3);
    float* vs  = (float*)(smc + SC_BC);    // overlay: used only before BC fills
    float* m2c = (float*)(smc + SC_M2);
    float* w4c = (float*)(smc + SC_W4C);
    float* b4s = (float*)(smc + SC_B4);

    int tid = threadIdx.x, w = tid >> 5, lane = tid & 31;
    int g = lane >> 2, tk = lane & 3;
    const float* w4g = hd ? e4w : s4w;

    for (int i = tid; i < NP; i += 512) {
        b3s[i] = g_b3[hd * NP + i];
        vs[i]  = g_st.v[hd][i];
    }
    if (tid < 16) b4s[tid] = (hd ? e4b : s4b)[tid];
    __syncthreads();

    // ---- A-build: fused pool-16 maxout of (G + v), split to bf16 hi/lo fragments
    {
        int mt = w & 7;
        int ksb = (w >> 3) ? 7 : 0;
        int kse = (w >> 3) ? 13 : 7;
        const float* gr0 = g_G + ((size_t)hd * T_LEN + t0 + mt * 16 + g) * NP;
        const float* gr1 = gr0 + (size_t)8 * NP;
        int fi = mt * 32 + lane;
        for (int ks = ksb; ks < kse; ks++) {
            int k0 = ks * 16 + 2 * tk;
            uint4 hi, lo;
            float a0 = maxout16(gr0 + (size_t)k0 * 16, vs + k0 * 16);
            float a1 = maxout16(gr0 + (size_t)(k0 + 1) * 16, vs + (k0 + 1) * 16);
            float b0 = maxout16(gr1 + (size_t)k0 * 16, vs + k0 * 16);
            float b1 = maxout16(gr1 + (size_t)(k0 + 1) * 16, vs + (k0 + 1) * 16);
            split_pack(a0, a1, hi.x, lo.x);
            split_pack(b0, b1, hi.y, lo.y);
            if (k0 + 8 < 200) {
                float a2 = maxout16(gr0 + (size_t)(k0 + 8) * 16, vs + (k0 + 8) * 16);
                float a3 = maxout16(gr0 + (size_t)(k0 + 9) * 16, vs + (k0 + 9) * 16);
                float b2 = maxout16(gr1 + (size_t)(k0 + 8) * 16, vs + (k0 + 8) * 16);
                float b3v = maxout16(gr1 + (size_t)(k0 + 9) * 16, vs + (k0 + 9) * 16);
                split_pack(a2, a3, hi.z, lo.z);
                split_pack(b2, b3v, hi.w, lo.w);
            } else { hi.z = hi.w = lo.z = lo.w = 0u; }
            AFH[ks * 256 + fi] = hi;
            AFL[ks * 256 + fi] = lo;
        }
    }
    __syncthreads();   // A-build done; vs dead; BC fills may start

    const uint4* Bsrc = g_w3f + (size_t)hd * 50 * 3328;
    // BC layout: [ks13][half2][256]. G0 = ks 0..6 (3584 u4), G1 = ks 7..12 (3072 u4)
#define SC_FILL(nc2)                                                           \
    {                                                                          \
        const uint4* s0 = Bsrc + (size_t)(2 * (nc2)) * 3328;                   \
        const uint4* s1 = Bsrc + (size_t)(2 * (nc2) + 1) * 3328;               \
        _Pragma("unroll")                                                      \
        for (int i_ = 0; i_ < 7; i_++) {                                       \
            int idx_ = tid + i_ * 512;              /* 0..3583 */              \
            int ks_ = idx_ >> 9, h_ = (idx_ >> 8) & 1, f_ = idx_ & 255;        \
            cp16(&BC[idx_], (h_ ? s1 : s0) + ks_ * 256 + f_);                  \
        }                                                                      \
        CP_COMMIT();                                                           \
        _Pragma("unroll")                                                      \
        for (int i_ = 0; i_ < 6; i_++) {                                       \
            int idx_ = 3584 + tid + i_ * 512;       /* 3584..6655 */           \
            int ks_ = idx_ >> 9, h_ = (idx_ >> 8) & 1, f_ = idx_ & 255;        \
            cp16(&BC[idx_], (h_ ? s1 : s0) + ks_ * 256 + f_);                  \
        }                                                                      \
        CP_COMMIT();                                                           \
    }

    SC_FILL(0);

    // ---- fc4 m1-part (overlaps chunk-0 B fill): m1 = hi + lo from fragments ----
    int row4 = tid >> 2, q4 = tid & 3;       // 4 threads per row, 4 p's each
    float p4[4];
#pragma unroll
    for (int i = 0; i < 4; i++) p4[i] = 0.f;
    {
        const float* w4r0 = w4g + (size_t)(q4 * 4 + 0) * 400;
        const float* w4r1 = w4g + (size_t)(q4 * 4 + 1) * 400;
        const float* w4r2 = w4g + (size_t)(q4 * 4 + 2) * 400;
        const float* w4r3 = w4g + (size_t)(q4 * 4 + 3) * 400;
        int mt = row4 >> 4, rem = row4 & 15, h = rem >> 3, gr = rem & 7;
        for (int ks = 0; ks < 13; ks++) {
#pragma unroll
            for (int tkk = 0; tkk < 4; tkk++) {
                int idx = ks * 256 + mt * 32 + gr * 4 + tkk;
                uint4 H = AFH[idx], L = AFL[idx];
                uint32_t ua = h ? H.y : H.x, la = h ? L.y : L.x;
                uint32_t ub = h ? H.w : H.z, lb = h ? L.w : L.z;
                int k0 = ks * 16 + 2 * tkk;
                float m0 = bf_lo(ua) + bf_lo(la);
                float m1v = bf_hi(ua) + bf_hi(la);
                p4[0] += m0 * w4r0[k0] + m1v * w4r0[k0 + 1];
                p4[1] += m0 * w4r1[k0] + m1v * w4r1[k0 + 1];
                p4[2] += m0 * w4r2[k0] + m1v * w4r2[k0 + 1];
                p4[3] += m0 * w4r3[k0] + m1v * w4r3[k0 + 1];
                if (k0 + 8 < 200) {
                    float m2 = bf_lo(ub) + bf_lo(lb);
                    float m3 = bf_hi(ub) + bf_hi(lb);
                    p4[0] += m2 * w4r0[k0 + 8] + m3 * w4r0[k0 + 9];
                    p4[1] += m2 * w4r1[k0 + 8] + m3 * w4r1[k0 + 9];
                    p4[2] += m2 * w4r2[k0 + 8] + m3 * w4r2[k0 + 9];
                    p4[3] += m2 * w4r3[k0 + 8] + m3 * w4r3[k0 + 9];
                }
            }
        }
    }

    int wm = w & 3, wn = w >> 2;   // warp tile: rows 32*wm, cols 32*wn (of 128-chunk)

    for (int nc2 = 0; nc2 < 25; nc2++) {
        float c[2][4][4];
#pragma unroll
        for (int m = 0; m < 2; m++)
#pragma unroll
            for (int n = 0; n < 4; n++)
#pragma unroll
                for (int q = 0; q < 4; q++) c[m][n][q] = 0.f;

        CP_WAIT(1);          // G0(nc2) complete
        __syncthreads();
        for (int ks = 0; ks < 7; ks++) {
            uint4 Bv[4];
#pragma unroll
            for (int n = 0; n < 4; n++)
                Bv[n] = BC[(ks * 2 + (wn >> 1)) * 256 + ((wn & 1) * 4 + n) * 32 + lane];
#pragma unroll
            for (int m = 0; m < 2; m++) {
                int mt = wm * 2 + m;
                uint4 Ah = AFH[ks * 256 + mt * 32 + lane];
                uint4 Al = AFL[ks * 256 + mt * 32 + lane];
#pragma unroll
                for (int n = 0; n < 4; n++) {
                    mma_bf(c[m][n], Ah, Bv[n].x, Bv[n].y);
                    mma_bf(c[m][n], Ah, Bv[n].z, Bv[n].w);
                    mma_bf(c[m][n], Al, Bv[n].x, Bv[n].y);
                }
            }
        }
        CP_WAIT(0);          // G1(nc2) complete
        __syncthreads();
        for (int ks = 7; ks < 13; ks++) {
            uint4 Bv[4];
#pragma unroll
            for (int n = 0; n < 4; n++)
                Bv[n] = BC[(ks * 2 + (wn >> 1)) * 256 + ((wn & 1) * 4 + n) * 32 + lane];
#pragma unroll
            for (int m = 0; m < 2; m++) {
                int mt = wm * 2 + m;
                uint4 Ah = AFH[ks * 256 + mt * 32 + lane];
                uint4 Al = AFL[ks * 256 + mt * 32 + lane];
#pragma unroll
                for (int n = 0; n < 4; n++) {
                    mma_bf(c[m][n], Ah, Bv[n].x, Bv[n].y);
                    mma_bf(c[m][n], Ah, Bv[n].z, Bv[n].w);
                    mma_bf(c[m][n], Al, Bv[n].x, Bv[n].y);
                }
            }
        }

        // maxout (pool 16) -> m2c[128][8]; stage w4c for this chunk
#pragma unroll
        for (int m = 0; m < 2; m++) {
            int rloc = wm * 32 + m * 16 + g;
#pragma unroll
            for (int grp = 0; grp < 2; grp++) {
                int n0 = grp * 2;
                int colb = nc2 * 128 + wn * 32 + grp * 16 + tk * 2;
                float b3a0 = b3s[colb],     b3a1 = b3s[colb + 1];
                float b3b0 = b3s[colb + 8], b3b1 = b3s[colb + 9];
                float vlo = fmaxf(fmaxf(c[m][n0][0] + b3a0, c[m][n0][1] + b3a1),
                                  fmaxf(c[m][n0 + 1][0] + b3b0, c[m][n0 + 1][1] + b3b1));
                float vhi = fmaxf(fmaxf(c[m][n0][2] + b3a0, c[m][n0][3] + b3a1),
                                  fmaxf(c[m][n0 + 1][2] + b3b0, c[m][n0 + 1][3] + b3b1));
                vlo = fmaxf(vlo, __shfl_xor_sync(0xffffffffu, vlo, 1));
                vlo = fmaxf(vlo, __shfl_xor_sync(0xffffffffu, vlo, 2));
                vhi = fmaxf(vhi, __shfl_xor_sync(0xffffffffu, vhi, 1));
                vhi = fmaxf(vhi, __shfl_xor_sync(0xffffffffu, vhi, 2));
                if (tk == 0) {
                    m2c[rloc * 8 + wn * 2 + grp] = vlo;
                    m2c[(rloc + 8) * 8 + wn * 2 + grp] = vhi;
                }
            }
        }
        if (tid < 128) {   // stage w4 cols for this chunk: w4c[jl][p]
            int jl = tid >> 4, p = tid & 15;
            w4c[jl * 16 + p] = w4g[(size_t)p * 400 + 200 + nc2 * 8 + jl];
        }
        __syncthreads();   // m2c/w4c visible; all BC reads complete

        if (nc2 + 1 < 25) SC_FILL(nc2 + 1);

        // fc4 partial from this chunk's 8 pooled values
        {
            const float* mrow = m2c + row4 * 8;
#pragma unroll
            for (int jl = 0; jl < 8; jl++) {
                float mv = mrow[jl];
                const float* wp = w4c + jl * 16 + q4 * 4;
#pragma unroll
                for (int pp = 0; pp < 4; pp++) p4[pp] += mv * wp[pp];
            }
        }
        __syncthreads();   // m2c/w4c reads done before next chunk's rewrite
    }
#undef SC_FILL

    // ---- final: pool-max over fc4, write alpha, warp-reduced packed argmax ----
    {
        float v = p4[0] + b4s[q4 * 4];
#pragma unroll
        for (int pp = 1; pp < 4; pp++) v = fmaxf(v, p4[pp] + b4s[q4 * 4 + pp]);
        v = fmaxf(v, __shfl_xor_sync(0xffffffffu, v, 1));
        v = fmaxf(v, __shfl_xor_sync(0xffffffffu, v, 2));
        if (q4 == 0) outh[t0 + row4] = v;
        int trow = t0 + row4;
        unsigned key = __float_as_uint(v);
        key = (key & 0x80000000u) ? ~key : (key | 0x80000000u);
        unsigned long long pk =
            ((unsigned long long)key << 32) | (unsigned long long)(0xFFFFFFFFu - (unsigned)trow);
#pragma unroll
        for (int o = 16; o; o >>= 1) {
            unsigned long long other = __shfl_xor_sync(0xffffffffu, pk, o);
            if (other > pk) pk = other;
        }
        if (lane == 0) atomicMax(&g_st.amax[hd], pk);
    }
}

// ---------------- argmax decode + done/start/end update ----------------
__global__ void k_update(int iter) {
    if (g_st.done) return;
    unsigned long long a0 = g_st.amax[0], a1 = g_st.amax[1];
    int ns = (int)(0xFFFFFFFFu - (unsigned)(a0 & 0xFFFFFFFFull));
    int ne = (int)(0xFFFFFFFFu - (unsigned)(a1 & 0xFFFFFFFFull));
    if (iter > 0 && ns == g_st.start && ne == g_st.end) g_st.done = 1;
    g_st.start = ns;
    g_st.end = ne;
}

// ---------------- launch ----------------
extern "C" void kernel_launch(void* const* d_in, const int* in_sizes, int n_in,
                              void* d_out, int out_size) {
    const float* U    = (const float*)d_in[0];
    const float* Wih  = (const float*)d_in[1];
    const float* Whh  = (const float*)d_in[2];
    const float* bih  = (const float*)d_in[3];
    const float* bhh  = (const float*)d_in[4];
    const float* s1w  = (const float*)d_in[5];
    const float* s2w  = (const float*)d_in[6];
    const float* s2b  = (const float*)d_in[7];
    const float* s3w  = (const float*)d_in[8];
    const float* s3b  = (const float*)d_in[9];
    const float* s4w  = (const float*)d_in[10];
    const float* s4b  = (const float*)d_in[11];
    const float* e1w  = (const float*)d_in[12];
    const float* e2w  = (const float*)d_in[13];
    const float* e2b  = (const float*)d_in[14];
    const float* e3w  = (const float*)d_in[15];
    const float* e3b  = (const float*)d_in[16];
    const float* e4w  = (const float*)d_in[17];
    const float* e4b  = (const float*)d_in[18];
    float* out = (float*)d_out;

    cudaFuncSetAttribute(k_score_mma, cudaFuncAttributeMaxDynamicSharedMemorySize, SC_SMEM);

    k_init<<<1, 256>>>();
    k_prep<<<6400, 128>>>(s2w, s2b, s3w, s3b, e2w, e2b, e3w, e3b);
    k_splitU<<<128, 256>>>(U);

    dim3 gG(25, 128, 2);
    k_gemm_G_mma<<<gG, 256>>>();

    for (int it = 0; it < 4; ++it) {
        k_gates<<<100, 256>>>(U, Wih, Whh, bih, bhh);
        k_act<<<1, 256>>>();
        k_r<<<50, 256>>>(U, s1w, e1w);
        k_v<<<800, 256>>>();
        dim3 gs(T_LEN / 128, 2);
        k_score_mma<<<gs, 512, SC_SMEM>>>(s4w, s4b, e4w, e4b, out, it);
        if (it < 3) k_update<<<1, 1>>>(it);
    }
}